// round 11
// baseline (speedup 1.0000x reference)
#include <cuda_runtime.h>
#include <math.h>
#include <stdint.h>

#define NNODES 100000
#define CIN    256
#define NHEADS 4
#define DHEAD  64
#define BPH    37
#define TILE   64
#define NT     ((NNODES + TILE - 1) / TILE)   // 1563
#define XS2    132                            // xsA float2 stride (==4 mod 16: clean)
#define KS     72                             // ks stride  (transposed-A clean)
#define QS     68                             // qs stride  (A-frag clean)
#define NTHR   256

// ---------------- helpers ----------------
__device__ __forceinline__ float rna(float f) {
    unsigned int u;
    asm("cvt.rna.tf32.f32 %0, %1;" : "=r"(u) : "f"(f));
    return __uint_as_float(u);
}
__device__ __forceinline__ unsigned int fu(float f) { return __float_as_uint(f); }
__device__ __forceinline__ void mma8(float c[4], uint4 a, uint2 b) {
    asm volatile("mma.sync.aligned.m16n8k8.row.col.f32.tf32.tf32.f32 "
        "{%0,%1,%2,%3}, {%4,%5,%6,%7}, {%8,%9}, {%0,%1,%2,%3};"
        : "+f"(c[0]), "+f"(c[1]), "+f"(c[2]), "+f"(c[3])
        : "r"(a.x), "r"(a.y), "r"(a.z), "r"(a.w), "r"(b.x), "r"(b.y));
}

// ---------------- device scratch ----------------
__device__ float g_part_kvs[BPH][NHEADS * DHEAD * CIN];
__device__ float g_part_kss[BPH][NHEADS * DHEAD];
__device__ float g_part_cs [BPH][CIN];
__device__ float g_kvs   [NHEADS * DHEAD * CIN];
__device__ float g_kssum [NHEADS * DHEAD];
__device__ float g_colsum[CIN];

extern __shared__ float smf[];

// =====================================================================
// Phase A  (256 threads; proj 16x32/warp, kv 32x64/warp; paired LDS.64)
// smem floats: xsA2 16896 | xsB2 16384 | wt2 16384 | ks 4608 | bias 64 |
//   kss 64 | red 512 | inv 64 | csred 2048 = 57024 (228096 B)
// =====================================================================
__global__ __launch_bounds__(NTHR, 1)
void phaseA_kernel(const float* __restrict__ x,
                   const float* __restrict__ Wk,
                   const float* __restrict__ bk)
{
    const int h = blockIdx.y, bx = blockIdx.x, tid = threadIdx.x;
    const int lane = tid & 31, w = tid >> 5;
    const int gq = lane >> 2, ct = lane & 3;

    float* xsA  = smf;             // float2[64][132]: {x[n][c], x[n][c+4]} pairs
    float* xsB  = xsA + 16896;     // float2[32][256]: {x[r][c], x[r+4][c]}, c^(p<<2)
    float* wt   = xsB + 16384;     // float2[128][64]: {w[c][m], w[c+4][m]}, m^(p<<2)
    float* ks   = wt  + 16384;     // [64][KS]
    float* bias = ks  + 4608;
    float* kss  = bias + 64;
    float* red  = kss + 64;        // [512]
    float* inv  = red + 512;       // [64]
    float* csred= inv + 64;        // [256][8]

    // stage Wk^T tf32 into row-paired layout
    for (int i = tid; i < 16384; i += NTHR) {
        int c = i >> 6, m = i & 63;
        int g = c >> 3, p = c & 3, half = (c >> 2) & 1;
        wt[(((g * 4 + p) * 64) + (m ^ (p << 2))) * 2 + half] =
            rna(Wk[(h * 64 + m) * 256 + c]);
    }
    if (tid < 64) { bias[tid] = bk[h * 64 + tid]; kss[tid] = 0.f; }

    const int ps = w >> 1, nh = w & 1;   // proj: 4 row-slabs x 2 col-halves
    const int km = w >> 2, cq = w & 3;   // kv:   2 m-slabs(32) x 4 c-quarters(64)

    float kvC[2][8][4];
    #pragma unroll
    for (int mi = 0; mi < 2; mi++)
        #pragma unroll
        for (int t = 0; t < 8; t++) {
            kvC[mi][t][0]=0.f; kvC[mi][t][1]=0.f; kvC[mi][t][2]=0.f; kvC[mi][t][3]=0.f;
        }
    // per-thread colsum partials: this thread touches columns lane*8 + e
    float csa[8];
    #pragma unroll
    for (int e = 0; e < 8; e++) csa[e] = 0.f;

    // quad mapping: per j: lane -> col8 block, qp = w + j*8 -> row pair
    float4 pf[16];
    {
        const int base = bx * TILE;
        const int valid = (NNODES - base < TILE) ? (NNODES - base) : TILE;
        #pragma unroll
        for (int j = 0; j < 4; j++) {
            int qp = w + j * 8;
            int g = qp >> 2, p = qp & 3;
            int n0 = g * 8 + p, n1 = n0 + 4;
            int c8 = lane * 8;
            const float* r0p = x + (size_t)(base + n0) * CIN + c8;
            const float* r1p = x + (size_t)(base + n1) * CIN + c8;
            float4 z = make_float4(0.f,0.f,0.f,0.f);
            pf[j*4+0] = (n0 < valid) ? *(const float4*)(r0p)     : z;
            pf[j*4+1] = (n0 < valid) ? *(const float4*)(r0p + 4) : z;
            pf[j*4+2] = (n1 < valid) ? *(const float4*)(r1p)     : z;
            pf[j*4+3] = (n1 < valid) ? *(const float4*)(r1p + 4) : z;
        }
    }
    __syncthreads();

    for (int tile = bx; tile < NT; tile += BPH) {
        // ---- store prefetched tile (both paired layouts) + per-column colsum
        #pragma unroll
        for (int j = 0; j < 4; j++) {
            int qp = w + j * 8;
            int g = qp >> 2, p = qp & 3;
            int n0 = g * 8 + p, n1 = n0 + 4;
            int c8 = lane * 8;
            float4 v0 = pf[j*4+0], v1 = pf[j*4+1], v2 = pf[j*4+2], v3 = pf[j*4+3];
            // v0: cols c8..c8+3 row n0; v1: cols c8+4..c8+7 row n0
            // v2: cols c8..c8+3 row n1; v3: cols c8+4..c8+7 row n1
            csa[0] += v0.x + v2.x;  csa[1] += v0.y + v2.y;
            csa[2] += v0.z + v2.z;  csa[3] += v0.w + v2.w;
            csa[4] += v1.x + v3.x;  csa[5] += v1.y + v3.y;
            csa[6] += v1.z + v3.z;  csa[7] += v1.w + v3.w;
            float4 f0 = make_float4(rna(v0.x), rna(v0.y), rna(v0.z), rna(v0.w));
            float4 f1 = make_float4(rna(v1.x), rna(v1.y), rna(v1.z), rna(v1.w));
            float4 f2 = make_float4(rna(v2.x), rna(v2.y), rna(v2.z), rna(v2.w));
            float4 f3 = make_float4(rna(v3.x), rna(v3.y), rna(v3.z), rna(v3.w));
            // xsA2 rows n0, n1 (col-pairs {c, c+4})
            float* a0 = xsA + (n0 * XS2 + lane * 4) * 2;
            *(float4*)(a0)     = make_float4(f0.x, f1.x, f0.y, f1.y);
            *(float4*)(a0 + 4) = make_float4(f0.z, f1.z, f0.w, f1.w);
            float* a1 = xsA + (n1 * XS2 + lane * 4) * 2;
            *(float4*)(a1)     = make_float4(f2.x, f3.x, f2.y, f3.y);
            *(float4*)(a1 + 4) = make_float4(f2.z, f3.z, f2.w, f3.w);
            // xsB2 row qp (row-pairs {n0, n1}), swizzled c^(p<<2)
            int s = p << 2;
            float* bbase = xsB + qp * 512;
            *(float4*)(bbase + ((c8 + 0) ^ s) * 2) = make_float4(f0.x, f2.x, f0.y, f2.y);
            *(float4*)(bbase + ((c8 + 2) ^ s) * 2) = make_float4(f0.z, f2.z, f0.w, f2.w);
            *(float4*)(bbase + ((c8 + 4) ^ s) * 2) = make_float4(f1.x, f3.x, f1.y, f3.y);
            *(float4*)(bbase + ((c8 + 6) ^ s) * 2) = make_float4(f1.z, f3.z, f1.w, f3.w);
        }
        __syncthreads();

        // ---- prefetch next tile
        if (tile + BPH < NT) {
            const int nb = (tile + BPH) * TILE;
            const int nv = (NNODES - nb < TILE) ? (NNODES - nb) : TILE;
            #pragma unroll
            for (int j = 0; j < 4; j++) {
                int qp = w + j * 8;
                int g = qp >> 2, p = qp & 3;
                int n0 = g * 8 + p, n1 = n0 + 4;
                int c8 = lane * 8;
                const float* r0p = x + (size_t)(nb + n0) * CIN + c8;
                const float* r1p = x + (size_t)(nb + n1) * CIN + c8;
                float4 z = make_float4(0.f,0.f,0.f,0.f);
                pf[j*4+0] = (n0 < nv) ? *(const float4*)(r0p)     : z;
                pf[j*4+1] = (n0 < nv) ? *(const float4*)(r0p + 4) : z;
                pf[j*4+2] = (n1 < nv) ? *(const float4*)(r1p)     : z;
                pf[j*4+3] = (n1 < nv) ? *(const float4*)(r1p + 4) : z;
            }
        }

        const int base = tile * TILE;
        const int valid = (NNODES - base < TILE) ? (NNODES - base) : TILE;

        // ---- k projection (16x32/warp) + fused row-norm partials
        {
            float pc[4][4];
            #pragma unroll
            for (int t = 0; t < 4; t++) { pc[t][0]=0.f; pc[t][1]=0.f; pc[t][2]=0.f; pc[t][3]=0.f; }
            #pragma unroll 4
            for (int kb = 0; kb < 32; kb++) {
                uint4 a;
                {
                    const float2 lo = *(const float2*)(xsA + ((ps*16+gq) * XS2 + kb*4 + ct) * 2);
                    const float2 hi = *(const float2*)(xsA + ((ps*16+gq+8) * XS2 + kb*4 + ct) * 2);
                    a.x = fu(lo.x); a.y = fu(hi.x); a.z = fu(lo.y); a.w = fu(hi.y);
                }
                #pragma unroll
                for (int t = 0; t < 4; t++) {
                    int nt = nh * 4 + t;
                    const float2 bp = *(const float2*)(
                        wt + ((kb*4 + ct) * 64 + ((nt*8+gq) ^ (ct << 2))) * 2);
                    uint2 b; b.x = fu(bp.x); b.y = fu(bp.y);
                    mma8(pc[t], a, b);
                }
            }
            int r0 = ps * 16 + gq;
            float nrm0 = 0.f, nrm1 = 0.f;
            #pragma unroll
            for (int t = 0; t < 4; t++) {
                int cb = (nh * 4 + t) * 8 + 2 * ct;
                float b0 = bias[cb], b1 = bias[cb + 1];
                float v0 = pc[t][0] + b0, v1 = pc[t][1] + b1;
                float v2 = pc[t][2] + b0, v3 = pc[t][3] + b1;
                *(float2*)(ks + r0 * KS + cb)       = make_float2(v0, v1);
                *(float2*)(ks + (r0 + 8) * KS + cb) = make_float2(v2, v3);
                nrm0 += v0 * v0 + v1 * v1;
                nrm1 += v2 * v2 + v3 * v3;
            }
            nrm0 += __shfl_xor_sync(0xffffffffu, nrm0, 1);
            nrm0 += __shfl_xor_sync(0xffffffffu, nrm0, 2);
            nrm1 += __shfl_xor_sync(0xffffffffu, nrm1, 1);
            nrm1 += __shfl_xor_sync(0xffffffffu, nrm1, 2);
            if (ct == 0) {
                red[r0 * 2 + nh]       = nrm0;
                red[(r0 + 8) * 2 + nh] = nrm1;
            }
        }
        __syncthreads();

        if (tid < 64) {
            float s = red[tid * 2] + red[tid * 2 + 1];
            inv[tid] = (tid < valid) ? rsqrtf(s) : 0.f;
        }
        __syncthreads();

        // ---- merged normalize + ks_sum partials
        {
            int m = tid & 63, rg = tid >> 6;
            float s = 0.f;
            #pragma unroll
            for (int r = 0; r < 16; r++) {
                int n = rg * 16 + r;
                float v = rna(ks[n * KS + m] * inv[n]);
                ks[n * KS + m] = v;
                s += v;
            }
            red[rg * 64 + m] = s;
        }
        __syncthreads();
        if (tid < 64)
            kss[tid] += red[tid] + red[64 + tid] + red[128 + tid] + red[192 + tid];

        // ---- kv += ks^T @ x  (32x64/warp; b via LDS.64 pairs)
        {
            #pragma unroll
            for (int kb = 0; kb < 8; kb++) {
                uint4 a0, a1;
                {
                    const float* kp = ks + (kb * 8 + ct) * KS + km * 32 + gq;
                    a0.x = fu(kp[0]);      a0.y = fu(kp[8]);
                    a0.z = fu(kp[4 * KS]); a0.w = fu(kp[4 * KS + 8]);
                    a1.x = fu(kp[16]);     a1.y = fu(kp[24]);
                    a1.z = fu(kp[4 * KS + 16]); a1.w = fu(kp[4 * KS + 24]);
                }
                const float* brow = xsB + (kb * 4 + ct) * 512;
                const int sw = ct << 2;
                #pragma unroll
                for (int t = 0; t < 8; t++) {
                    int c = cq * 64 + t * 8 + gq;
                    const float2 bp = *(const float2*)(brow + (c ^ sw) * 2);
                    uint2 b; b.x = fu(bp.x); b.y = fu(bp.y);
                    mma8(kvC[0][t], a0, b);
                    mma8(kvC[1][t], a1, b);
                }
            }
        }
        __syncthreads();
    }

    // ---- deterministic per-block partials
    {
        float* dst = g_part_kvs[bx] + h * (DHEAD * CIN);
        #pragma unroll
        for (int mi = 0; mi < 2; mi++)
            #pragma unroll
            for (int t = 0; t < 8; t++) {
                int c0 = cq * 64 + t * 8 + 2 * ct;
                int m0 = km * 32 + mi * 16 + gq;
                dst[m0 * 256 + c0]           = kvC[mi][t][0];
                dst[m0 * 256 + c0 + 1]       = kvC[mi][t][1];
                dst[(m0 + 8) * 256 + c0]     = kvC[mi][t][2];
                dst[(m0 + 8) * 256 + c0 + 1] = kvC[mi][t][3];
            }
    }
    if (tid < 64) g_part_kss[bx][h * 64 + tid] = kss[tid];
    // colsum: column lane*8+e, warp-partial w
    {
        #pragma unroll
        for (int e = 0; e < 8; e++)
            csred[(lane * 8 + e) * 8 + w] = csa[e];
    }
    __syncthreads();
    if (h == 0) {
        float s = 0.f;
        #pragma unroll
        for (int j = 0; j < 8; j++) s += csred[tid * 8 + j];
        g_part_cs[bx][tid] = s;
    }
}

// =====================================================================
// Reduce
// =====================================================================
__global__ void reduce_kernel()
{
    int i = blockIdx.x * 256 + threadIdx.x;
    if (i < NHEADS * DHEAD * CIN) {
        float s = 0.f;
        #pragma unroll 1
        for (int b = 0; b < BPH; b++) s += g_part_kvs[b][i];
        g_kvs[i] = s;
    }
    if (i < NHEADS * DHEAD) {
        float s = 0.f;
        for (int b = 0; b < BPH; b++) s += g_part_kss[b][i];
        g_kssum[i] = s;
    }
    if (i < CIN) {
        float s = 0.f;
        for (int b = 0; b < BPH; b++) s += g_part_cs[b][i];
        g_colsum[i] = s;
    }
}

// =====================================================================
// Phase B  (256 threads; proj 16x32/warp, out 32x64/warp; paired LDS.64)
// smem floats: xsA2 16896 | wt2 16384 | kvs2 16384 | qs 4352 | bias 64 |
//   kss 64 | cs 256 | red 128 | red2 128 | inv 64 | rno 64 = 54784 (219136 B)
// =====================================================================
__global__ __launch_bounds__(NTHR, 1)
void phaseB_kernel(const float* __restrict__ x,
                   const float* __restrict__ Wq,
                   const float* __restrict__ bq,
                   float* __restrict__ out)
{
    const int h = blockIdx.y, tid = threadIdx.x;
    const int lane = tid & 31, w = tid >> 5;
    const int gq = lane >> 2, ct = lane & 3;

    float* xsA  = smf;             // float2[64][132]
    float* wt   = xsA + 16896;     // float2[128][64]
    float* kvs  = wt  + 16384;     // float2[32][256] row-paired, c^(p<<2)
    float* qs   = kvs + 16384;     // [64][QS]
    float* bias = qs  + 4352;
    float* kss  = bias + 64;
    float* cs   = kss + 64;
    float* red  = cs  + 256;       // [128]
    float* red2 = red + 128;       // [128]
    float* inv  = red2 + 128;      // [64]
    float* rno  = inv + 64;        // [64]

    for (int i = tid; i < 16384; i += NTHR) {
        int c = i >> 6, m = i & 63;
        int g = c >> 3, p = c & 3, half = (c >> 2) & 1;
        wt[(((g * 4 + p) * 64) + (m ^ (p << 2))) * 2 + half] =
            rna(Wq[(h * 64 + m) * 256 + c]);
    }
    for (int i = tid; i < 16384; i += NTHR) {
        int m = i >> 8, c = i & 255;
        int g = m >> 3, p = m & 3, half = (m >> 2) & 1;
        kvs[(((g * 4 + p) * 256) + (c ^ (p << 2))) * 2 + half] =
            rna(g_kvs[h * 16384 + m * 256 + c]);
    }
    if (tid < 64) { bias[tid] = bq[h * 64 + tid]; kss[tid] = g_kssum[h * 64 + tid]; }
    cs[tid] = g_colsum[tid];

    const int ps = w >> 1, nh = w & 1;   // proj
    const int sn = w >> 2, cq = w & 3;   // out: 2 row-slabs(32) x 4 c-quarters(64)

    float4 pf[16];
    {
        const int base = blockIdx.x * TILE;
        const int valid = (NNODES - base < TILE) ? (NNODES - base) : TILE;
        #pragma unroll
        for (int j = 0; j < 8; j++) {
            int s = tid + j * 256;
            int n = s >> 5, c8 = (s & 31) * 8;
            const float* rp = x + (size_t)(base + n) * CIN + c8;
            float4 z = make_float4(0.f,0.f,0.f,0.f);
            pf[j*2+0] = (n < valid) ? *(const float4*)(rp)     : z;
            pf[j*2+1] = (n < valid) ? *(const float4*)(rp + 4) : z;
        }
    }
    __syncthreads();

    for (int tile = blockIdx.x; tile < NT; tile += BPH) {
        #pragma unroll
        for (int j = 0; j < 8; j++) {
            int s = tid + j * 256;
            int n = s >> 5, c8g = s & 31;
            float4 v0 = pf[j*2+0], v1 = pf[j*2+1];
            float4 f0 = make_float4(rna(v0.x), rna(v0.y), rna(v0.z), rna(v0.w));
            float4 f1 = make_float4(rna(v1.x), rna(v1.y), rna(v1.z), rna(v1.w));
            float* a0 = xsA + (n * XS2 + c8g * 4) * 2;
            *(float4*)(a0)     = make_float4(f0.x, f1.x, f0.y, f1.y);
            *(float4*)(a0 + 4) = make_float4(f0.z, f1.z, f0.w, f1.w);
        }
        __syncthreads();

        if (tile + BPH < NT) {
            const int nb = (tile + BPH) * TILE;
            const int nv = (NNODES - nb < TILE) ? (NNODES - nb) : TILE;
            #pragma unroll
            for (int j = 0; j < 8; j++) {
                int s = tid + j * 256;
                int n = s >> 5, c8 = (s & 31) * 8;
                const float* rp = x + (size_t)(nb + n) * CIN + c8;
                float4 z = make_float4(0.f,0.f,0.f,0.f);
                pf[j*2+0] = (n < nv) ? *(const float4*)(rp)     : z;
                pf[j*2+1] = (n < nv) ? *(const float4*)(rp + 4) : z;
            }
        }

        const int base = tile * TILE;
        const int valid = (NNODES - base < TILE) ? (NNODES - base) : TILE;

        // ---- q projection + fused row-norm & ks_sum-dot partials
        {
            float pc[4][4];
            #pragma unroll
            for (int t = 0; t < 4; t++) { pc[t][0]=0.f; pc[t][1]=0.f; pc[t][2]=0.f; pc[t][3]=0.f; }
            #pragma unroll 4
            for (int kb = 0; kb < 32; kb++) {
                uint4 a;
                {
                    const float2 lo = *(const float2*)(xsA + ((ps*16+gq) * XS2 + kb*4 + ct) * 2);
                    const float2 hi = *(const float2*)(xsA + ((ps*16+gq+8) * XS2 + kb*4 + ct) * 2);
                    a.x = fu(lo.x); a.y = fu(hi.x); a.z = fu(lo.y); a.w = fu(hi.y);
                }
                #pragma unroll
                for (int t = 0; t < 4; t++) {
                    int nt = nh * 4 + t;
                    const float2 bp = *(const float2*)(
                        wt + ((kb*4 + ct) * 64 + ((nt*8+gq) ^ (ct << 2))) * 2);
                    uint2 b; b.x = fu(bp.x); b.y = fu(bp.y);
                    mma8(pc[t], a, b);
                }
            }
            int r0 = ps * 16 + gq;
            float nrm0 = 0.f, nrm1 = 0.f, dot0 = 0.f, dot1 = 0.f;
            #pragma unroll
            for (int t = 0; t < 4; t++) {
                int cb = (nh * 4 + t) * 8 + 2 * ct;
                float b0 = bias[cb], b1 = bias[cb + 1];
                float k0 = kss[cb],  k1 = kss[cb + 1];
                float v0 = pc[t][0] + b0, v1 = pc[t][1] + b1;
                float v2 = pc[t][2] + b0, v3 = pc[t][3] + b1;
                *(float2*)(qs + r0 * QS + cb)       = make_float2(v0, v1);
                *(float2*)(qs + (r0 + 8) * QS + cb) = make_float2(v2, v3);
                nrm0 += v0 * v0 + v1 * v1;  dot0 += v0 * k0 + v1 * k1;
                nrm1 += v2 * v2 + v3 * v3;  dot1 += v2 * k0 + v3 * k1;
            }
            nrm0 += __shfl_xor_sync(0xffffffffu, nrm0, 1);
            nrm0 += __shfl_xor_sync(0xffffffffu, nrm0, 2);
            nrm1 += __shfl_xor_sync(0xffffffffu, nrm1, 1);
            nrm1 += __shfl_xor_sync(0xffffffffu, nrm1, 2);
            dot0 += __shfl_xor_sync(0xffffffffu, dot0, 1);
            dot0 += __shfl_xor_sync(0xffffffffu, dot0, 2);
            dot1 += __shfl_xor_sync(0xffffffffu, dot1, 1);
            dot1 += __shfl_xor_sync(0xffffffffu, dot1, 2);
            if (ct == 0) {
                red [r0 * 2 + nh] = nrm0;  red [(r0 + 8) * 2 + nh] = nrm1;
                red2[r0 * 2 + nh] = dot0;  red2[(r0 + 8) * 2 + nh] = dot1;
            }
        }
        __syncthreads();

        if (tid < 64) {
            float s = red [tid * 2] + red [tid * 2 + 1];
            float d = red2[tid * 2] + red2[tid * 2 + 1];
            float iv = rsqrtf(s);
            inv[tid] = iv;
            rno[tid] = 1.0f / (iv * d + (float)NNODES);
        }
        __syncthreads();
        {
            int m = tid & 63, rg = tid >> 6;
            #pragma unroll
            for (int r = 0; r < 16; r++) {
                int n = rg * 16 + r;
                qs[n * QS + m] = rna(qs[n * QS + m] * inv[n]);
            }
        }
        __syncthreads();

        // ---- out = (qs @ kvs + colsum) * rno   (32x64/warp; b via LDS.64)
        {
            float oc[2][8][4];
            #pragma unroll
            for (int mi = 0; mi < 2; mi++)
                #pragma unroll
                for (int t = 0; t < 8; t++) {
                    oc[mi][t][0]=0.f; oc[mi][t][1]=0.f; oc[mi][t][2]=0.f; oc[mi][t][3]=0.f;
                }
            #pragma unroll
            for (int kb = 0; kb < 8; kb++) {
                uint4 a0, a1;
                {
                    const float* ap = qs + (sn * 32 + gq) * QS + kb * 8 + ct;
                    a0.x = fu(ap[0]); a0.y = fu(ap[8 * QS]);
                    a0.z = fu(ap[4]); a0.w = fu(ap[8 * QS + 4]);
                    const float* ap1 = ap + 16 * QS;
                    a1.x = fu(ap1[0]); a1.y = fu(ap1[8 * QS]);
                    a1.z = fu(ap1[4]); a1.w = fu(ap1[8 * QS + 4]);
                }
                const float* brow = kvs + (kb * 4 + ct) * 512;
                const int sw = ct << 2;
                #pragma unroll
                for (int t = 0; t < 8; t++) {
                    int c = cq * 64 + t * 8 + gq;
                    const float2 bp = *(const float2*)(brow + (c ^ sw) * 2);
                    uint2 b; b.x = fu(bp.x); b.y = fu(bp.y);
                    mma8(oc[0][t], a0, b);
                    mma8(oc[1][t], a1, b);
                }
            }
            #pragma unroll
            for (int mi = 0; mi < 2; mi++) {
                int n0 = sn * 32 + mi * 16 + gq;
                float r0v = rno[n0], r1v = rno[n0 + 8];
                #pragma unroll
                for (int t = 0; t < 8; t++) {
                    int c0 = cq * 64 + t * 8 + 2 * ct;
                    float cv0 = cs[c0], cv1 = cs[c0 + 1];
                    if (n0 < valid)
                        *(float2*)(out + (size_t)(base + n0) * (NHEADS * CIN) + h * CIN + c0) =
                            make_float2((oc[mi][t][0] + cv0) * r0v, (oc[mi][t][1] + cv1) * r0v);
                    if (n0 + 8 < valid)
                        *(float2*)(out + (size_t)(base + n0 + 8) * (NHEADS * CIN) + h * CIN + c0) =
                            make_float2((oc[mi][t][2] + cv0) * r1v, (oc[mi][t][3] + cv1) * r1v);
                }
            }
        }
        __syncthreads();
    }
}

// =====================================================================
extern "C" void kernel_launch(void* const* d_in, const int* in_sizes, int n_in,
                              void* d_out, int out_size)
{
    const float* x    = (const float*)d_in[0];
    const float* Wq_w = (const float*)d_in[1];
    const float* Wq_b = (const float*)d_in[2];
    const float* Wk_w = (const float*)d_in[3];
    const float* Wk_b = (const float*)d_in[4];
    float* out = (float*)d_out;

    const int smemA = 57024 * (int)sizeof(float);   // 228096 B
    const int smemB = 54784 * (int)sizeof(float);   // 219136 B

    cudaFuncSetAttribute(phaseA_kernel, cudaFuncAttributeMaxDynamicSharedMemorySize, smemA);
    cudaFuncSetAttribute(phaseB_kernel, cudaFuncAttributeMaxDynamicSharedMemorySize, smemB);

    phaseA_kernel<<<dim3(BPH, NHEADS), NTHR, smemA>>>(x, Wk_w, Wk_b);
    reduce_kernel<<<256, 256>>>();
    phaseB_kernel<<<dim3(BPH, NHEADS), NTHR, smemB>>>(x, Wq_w, Wq_b, out);
}

// round 12
// speedup vs baseline: 1.0335x; 1.0335x over previous
#include <cuda_runtime.h>
#include <math.h>
#include <stdint.h>

#define NNODES 100000
#define CIN    256
#define NHEADS 4
#define DHEAD  64
#define BPH    37
#define TILE   64
#define NT     ((NNODES + TILE - 1) / TILE)   // 1563
#define XS     260                            // xsA stride (A-frag clean)
#define KS     72                             // ks stride  (transposed-A clean)
#define QS     68                             // qs stride  (A-frag clean)
#define NTHR   256

// ---------------- helpers ----------------
__device__ __forceinline__ float rna(float f) {
    unsigned int u;
    asm("cvt.rna.tf32.f32 %0, %1;" : "=r"(u) : "f"(f));
    return __uint_as_float(u);
}
__device__ __forceinline__ unsigned int fu(float f) { return __float_as_uint(f); }
__device__ __forceinline__ void mma8(float c[4], uint4 a, uint2 b) {
    asm volatile("mma.sync.aligned.m16n8k8.row.col.f32.tf32.tf32.f32 "
        "{%0,%1,%2,%3}, {%4,%5,%6,%7}, {%8,%9}, {%0,%1,%2,%3};"
        : "+f"(c[0]), "+f"(c[1]), "+f"(c[2]), "+f"(c[3])
        : "r"(a.x), "r"(a.y), "r"(a.z), "r"(a.w), "r"(b.x), "r"(b.y));
}

// ---------------- device scratch ----------------
__device__ float g_part_kvs[BPH][NHEADS * DHEAD * CIN];
__device__ float g_part_kss[BPH][NHEADS * DHEAD];
__device__ float g_part_cs [BPH][CIN];
__device__ float g_kvs   [NHEADS * DHEAD * CIN];
__device__ float g_kssum [NHEADS * DHEAD];
__device__ float g_colsum[CIN];

extern __shared__ float smf[];

// =====================================================================
// Phase A  (256 threads; proj 16x32/warp, kv 32x64/warp)
// smem floats: xsA 16640 | xsB 16384 | wt 16384 | ks 4608 | bias 64 |
//   kss 64 | red 512 | inv 64 | csred 1024 = 55744 (222976 B)
// =====================================================================
__global__ __launch_bounds__(NTHR, 1)
void phaseA_kernel(const float* __restrict__ x,
                   const float* __restrict__ Wk,
                   const float* __restrict__ bk)
{
    const int h = blockIdx.y, bx = blockIdx.x, tid = threadIdx.x;
    const int lane = tid & 31, w = tid >> 5;
    const int gq = lane >> 2, ct = lane & 3;

    float* xsA  = smf;             // [64][260]
    float* xsB  = xsA + 16640;     // [64][256] swizzled: phys_c = c ^ (8*(n&3))
    float* wt   = xsB + 16384;     // [256][64] swizzled: phys_m = m ^ (8*(c&3))
    float* ks   = wt  + 16384;     // [64][KS] raw (bias added, NOT normalized)
    float* bias = ks  + 4608;
    float* kss  = bias + 64;
    float* red  = kss + 64;        // [512]
    float* inv  = red + 512;       // [64]
    float* csred= inv + 64;        // [256][4]

    for (int i = tid; i < 16384; i += NTHR) {
        int c = i >> 6, m = i & 63;
        wt[c * 64 + (m ^ (8 * (c & 3)))] = rna(Wk[(h * 64 + m) * 256 + c]);
    }
    if (tid < 64) { bias[tid] = bk[h * 64 + tid]; kss[tid] = 0.f; }

    const int ps = w >> 1, nh = w & 1;   // proj: 4 row-slabs x 2 col-halves
    const int km = w >> 2, cq = w & 3;   // kv:   2 m-slabs(32) x 4 c-quarters(64)

    float kvC[2][8][4];
    #pragma unroll
    for (int mi = 0; mi < 2; mi++)
        #pragma unroll
        for (int t = 0; t < 8; t++) {
            kvC[mi][t][0]=0.f; kvC[mi][t][1]=0.f; kvC[mi][t][2]=0.f; kvC[mi][t][3]=0.f;
        }
    float4 csacc = make_float4(0.f, 0.f, 0.f, 0.f);

    // prefetch first HALF tile (rows 0..31)
    float4 pf[8];
    {
        const int base = bx * TILE;
        const int valid = (NNODES - base < TILE) ? (NNODES - base) : TILE;
        #pragma unroll
        for (int j = 0; j < 8; j++) {
            int i = tid + j * NTHR;
            int n = i >> 6, c4 = (i & 63) << 2;
            pf[j] = (n < valid) ? *(const float4*)(x + (size_t)(base + n) * CIN + c4)
                                : make_float4(0.f, 0.f, 0.f, 0.f);
        }
    }
    __syncthreads();

    for (int tile = bx; tile < NT; tile += BPH) {
        const int base = tile * TILE;
        const int valid = (NNODES - base < TILE) ? (NNODES - base) : TILE;

        // ---- store tile: first half from pf, second half loaded directly
        #pragma unroll
        for (int j = 0; j < 8; j++) {
            int i = tid + j * NTHR;
            int n = i >> 6, c4 = (i & 63) << 2;
            float4 v = pf[j];
            csacc.x += v.x; csacc.y += v.y; csacc.z += v.z; csacc.w += v.w;
            float4 r = make_float4(rna(v.x), rna(v.y), rna(v.z), rna(v.w));
            *(float4*)(xsA + n * XS + c4) = r;
            *(float4*)(xsB + n * 256 + (c4 ^ (8 * (n & 3)))) = r;
        }
        #pragma unroll
        for (int j = 8; j < 16; j++) {
            int i = tid + j * NTHR;
            int n = i >> 6, c4 = (i & 63) << 2;
            float4 v = (n < valid) ? *(const float4*)(x + (size_t)(base + n) * CIN + c4)
                                   : make_float4(0.f, 0.f, 0.f, 0.f);
            csacc.x += v.x; csacc.y += v.y; csacc.z += v.z; csacc.w += v.w;
            float4 r = make_float4(rna(v.x), rna(v.y), rna(v.z), rna(v.w));
            *(float4*)(xsA + n * XS + c4) = r;
            *(float4*)(xsB + n * 256 + (c4 ^ (8 * (n & 3)))) = r;
        }
        __syncthreads();

        // ---- prefetch next tile's first half (overlaps mma work)
        if (tile + BPH < NT) {
            const int nb = (tile + BPH) * TILE;
            const int nv = (NNODES - nb < TILE) ? (NNODES - nb) : TILE;
            #pragma unroll
            for (int j = 0; j < 8; j++) {
                int i = tid + j * NTHR;
                int n = i >> 6, c4 = (i & 63) << 2;
                pf[j] = (n < nv) ? *(const float4*)(x + (size_t)(nb + n) * CIN + c4)
                                 : make_float4(0.f, 0.f, 0.f, 0.f);
            }
        }

        // ---- k projection (16x32/warp) + fused row-norm partials
        {
            float pc[4][4];
            #pragma unroll
            for (int t = 0; t < 4; t++) { pc[t][0]=0.f; pc[t][1]=0.f; pc[t][2]=0.f; pc[t][3]=0.f; }
            #pragma unroll 4
            for (int kb = 0; kb < 32; kb++) {
                const float* xr = xsA + (ps * 16 + gq) * XS + kb * 8 + ct;
                uint4 a;
                a.x = fu(xr[0]); a.y = fu(xr[8 * XS]);
                a.z = fu(xr[4]); a.w = fu(xr[8 * XS + 4]);
                #pragma unroll
                for (int t = 0; t < 4; t++) {
                    int nt = nh * 4 + t;
                    const float* wp = wt + (kb * 8 + ct) * 64 + ((nt * 8 + gq) ^ (8 * ct));
                    uint2 b; b.x = fu(wp[0]); b.y = fu(wp[4 * 64]);
                    mma8(pc[t], a, b);
                }
            }
            int r0 = ps * 16 + gq;
            float nrm0 = 0.f, nrm1 = 0.f;
            #pragma unroll
            for (int t = 0; t < 4; t++) {
                int cb = (nh * 4 + t) * 8 + 2 * ct;
                float b0 = bias[cb], b1 = bias[cb + 1];
                float v0 = pc[t][0] + b0, v1 = pc[t][1] + b1;
                float v2 = pc[t][2] + b0, v3 = pc[t][3] + b1;
                *(float2*)(ks + r0 * KS + cb)       = make_float2(v0, v1);
                *(float2*)(ks + (r0 + 8) * KS + cb) = make_float2(v2, v3);
                nrm0 += v0 * v0 + v1 * v1;
                nrm1 += v2 * v2 + v3 * v3;
            }
            nrm0 += __shfl_xor_sync(0xffffffffu, nrm0, 1);
            nrm0 += __shfl_xor_sync(0xffffffffu, nrm0, 2);
            nrm1 += __shfl_xor_sync(0xffffffffu, nrm1, 1);
            nrm1 += __shfl_xor_sync(0xffffffffu, nrm1, 2);
            if (ct == 0) {
                red[r0 * 2 + nh]       = nrm0;
                red[(r0 + 8) * 2 + nh] = nrm1;
            }
        }
        __syncthreads();

        if (tid < 64) {
            float s = red[tid * 2] + red[tid * 2 + 1];
            inv[tid] = (tid < valid) ? rsqrtf(s) : 0.f;
        }
        __syncthreads();

        // ---- ks_sum partials from raw ks (normalize folded; no STS pass)
        {
            int m = tid & 63, rg = tid >> 6;
            float s = 0.f;
            #pragma unroll
            for (int r = 0; r < 16; r++) {
                int n = rg * 16 + r;
                s += rna(ks[n * KS + m] * inv[n]);
            }
            red[rg * 64 + m] = s;
        }
        __syncthreads();
        if (tid < 64)
            kss[tid] += red[tid] + red[64 + tid] + red[128 + tid] + red[192 + tid];

        // ---- kv += ks^T @ x  (32x64/warp; normalization folded into A-frags)
        {
            #pragma unroll
            for (int kb = 0; kb < 8; kb++) {
                int n0 = kb * 8 + ct;
                float iv0 = inv[n0], iv1 = inv[n0 + 4];
                uint4 a0, a1;
                {
                    const float* kp = ks + n0 * KS + km * 32 + gq;
                    a0.x = fu(rna(kp[0]  * iv0));          a0.y = fu(rna(kp[8]  * iv0));
                    a0.z = fu(rna(kp[4 * KS] * iv1));      a0.w = fu(rna(kp[4 * KS + 8] * iv1));
                    a1.x = fu(rna(kp[16] * iv0));          a1.y = fu(rna(kp[24] * iv0));
                    a1.z = fu(rna(kp[4 * KS + 16] * iv1)); a1.w = fu(rna(kp[4 * KS + 24] * iv1));
                }
                const float* xb0 = xsB + n0 * 256;
                const float* xb1 = xsB + (n0 + 4) * 256;
                const int sw = 8 * ct;
                #pragma unroll
                for (int t = 0; t < 8; t++) {
                    int c = cq * 64 + t * 8 + gq;
                    uint2 b; b.x = fu(xb0[c ^ sw]); b.y = fu(xb1[c ^ sw]);
                    mma8(kvC[0][t], a0, b);
                    mma8(kvC[1][t], a1, b);
                }
            }
        }
        __syncthreads();
    }

    // ---- deterministic per-block partials
    {
        float* dst = g_part_kvs[bx] + h * (DHEAD * CIN);
        #pragma unroll
        for (int mi = 0; mi < 2; mi++)
            #pragma unroll
            for (int t = 0; t < 8; t++) {
                int c0 = cq * 64 + t * 8 + 2 * ct;
                int m0 = km * 32 + mi * 16 + gq;
                dst[m0 * 256 + c0]           = kvC[mi][t][0];
                dst[m0 * 256 + c0 + 1]       = kvC[mi][t][1];
                dst[(m0 + 8) * 256 + c0]     = kvC[mi][t][2];
                dst[(m0 + 8) * 256 + c0 + 1] = kvC[mi][t][3];
            }
    }
    if (tid < 64) g_part_kss[bx][h * 64 + tid] = kss[tid];
    {
        int c4 = (tid & 63) * 4, grp = tid >> 6;
        csred[(c4+0)*4+grp] = csacc.x; csred[(c4+1)*4+grp] = csacc.y;
        csred[(c4+2)*4+grp] = csacc.z; csred[(c4+3)*4+grp] = csacc.w;
    }
    __syncthreads();
    if (h == 0)
        g_part_cs[bx][tid] = csred[tid*4] + csred[tid*4+1] + csred[tid*4+2] + csred[tid*4+3];
}

// =====================================================================
// Reduce
// =====================================================================
__global__ void reduce_kernel()
{
    int i = blockIdx.x * 256 + threadIdx.x;
    if (i < NHEADS * DHEAD * CIN) {
        float s = 0.f;
        #pragma unroll 1
        for (int b = 0; b < BPH; b++) s += g_part_kvs[b][i];
        g_kvs[i] = s;
    }
    if (i < NHEADS * DHEAD) {
        float s = 0.f;
        for (int b = 0; b < BPH; b++) s += g_part_kss[b][i];
        g_kssum[i] = s;
    }
    if (i < CIN) {
        float s = 0.f;
        for (int b = 0; b < BPH; b++) s += g_part_cs[b][i];
        g_colsum[i] = s;
    }
}

// =====================================================================
// Phase B  (256 threads; proj 16x32/warp, out 32x64/warp)
// smem floats: xsA 16640 | wt 16384 | kvs 16384 | qs 4352 | bias 64 |
//   kss 64 | cs 256 | red 128 | red2 128 | inv 64 | rno 64 = 54528 (218112 B)
// =====================================================================
__global__ __launch_bounds__(NTHR, 1)
void phaseB_kernel(const float* __restrict__ x,
                   const float* __restrict__ Wq,
                   const float* __restrict__ bq,
                   float* __restrict__ out)
{
    const int h = blockIdx.y, tid = threadIdx.x;
    const int lane = tid & 31, w = tid >> 5;
    const int gq = lane >> 2, ct = lane & 3;

    float* xsA  = smf;             // [64][260]
    float* wt   = xsA + 16640;     // [256][64] swizzled
    float* kvs  = wt  + 16384;     // [64][256] swizzled: phys_c = c ^ (8*(m&3))
    float* qs   = kvs + 16384;     // [64][QS] raw (bias added, NOT normalized)
    float* bias = qs  + 4352;
    float* kss  = bias + 64;
    float* cs   = kss + 64;
    float* red  = cs  + 256;       // [128]
    float* red2 = red + 128;       // [128]
    float* inv  = red2 + 128;      // [64]
    float* rno  = inv + 64;        // [64]

    for (int i = tid; i < 16384; i += NTHR) {
        int c = i >> 6, m = i & 63;
        wt[c * 64 + (m ^ (8 * (c & 3)))] = rna(Wq[(h * 64 + m) * 256 + c]);
    }
    for (int i = tid; i < 16384; i += NTHR) {
        int m = i >> 8, c = i & 255;
        kvs[m * 256 + (c ^ (8 * (m & 3)))] = rna(g_kvs[h * 16384 + m * 256 + c]);
    }
    if (tid < 64) { bias[tid] = bq[h * 64 + tid]; kss[tid] = g_kssum[h * 64 + tid]; }
    cs[tid] = g_colsum[tid];

    const int ps = w >> 1, nh = w & 1;   // proj
    const int sn = w >> 2, cq = w & 3;   // out: 2 row-slabs(32) x 4 c-quarters(64)

    // prefetch first half (8 slots of 16)
    float4 pf[8];
    {
        const int base = blockIdx.x * TILE;
        const int valid = (NNODES - base < TILE) ? (NNODES - base) : TILE;
        #pragma unroll
        for (int j = 0; j < 4; j++) {
            int s = tid + j * 256;
            int n = s >> 5, c8 = (s & 31) * 8;
            const float* rp = x + (size_t)(base + n) * CIN + c8;
            float4 z = make_float4(0.f,0.f,0.f,0.f);
            pf[j*2+0] = (n < valid) ? *(const float4*)(rp)     : z;
            pf[j*2+1] = (n < valid) ? *(const float4*)(rp + 4) : z;
        }
    }
    __syncthreads();

    for (int tile = blockIdx.x; tile < NT; tile += BPH) {
        const int base = tile * TILE;
        const int valid = (NNODES - base < TILE) ? (NNODES - base) : TILE;

        // ---- store tile: first half from pf, second half direct
        #pragma unroll
        for (int j = 0; j < 4; j++) {
            int s = tid + j * 256;
            int n = s >> 5, c8g = s & 31;
            float4 v0 = pf[j*2+0], v1 = pf[j*2+1];
            float* a0 = xsA + n * XS + c8g * 8;
            *(float4*)(a0)     = make_float4(rna(v0.x), rna(v0.y), rna(v0.z), rna(v0.w));
            *(float4*)(a0 + 4) = make_float4(rna(v1.x), rna(v1.y), rna(v1.z), rna(v1.w));
        }
        #pragma unroll
        for (int j = 4; j < 8; j++) {
            int s = tid + j * 256;
            int n = s >> 5, c8g = s & 31;
            const float* rp = x + (size_t)(base + n) * CIN + c8g * 8;
            float4 z = make_float4(0.f,0.f,0.f,0.f);
            float4 v0 = (n < valid) ? *(const float4*)(rp)     : z;
            float4 v1 = (n < valid) ? *(const float4*)(rp + 4) : z;
            float* a0 = xsA + n * XS + c8g * 8;
            *(float4*)(a0)     = make_float4(rna(v0.x), rna(v0.y), rna(v0.z), rna(v0.w));
            *(float4*)(a0 + 4) = make_float4(rna(v1.x), rna(v1.y), rna(v1.z), rna(v1.w));
        }
        __syncthreads();

        if (tile + BPH < NT) {
            const int nb = (tile + BPH) * TILE;
            const int nv = (NNODES - nb < TILE) ? (NNODES - nb) : TILE;
            #pragma unroll
            for (int j = 0; j < 4; j++) {
                int s = tid + j * 256;
                int n = s >> 5, c8 = (s & 31) * 8;
                const float* rp = x + (size_t)(nb + n) * CIN + c8;
                float4 z = make_float4(0.f,0.f,0.f,0.f);
                pf[j*2+0] = (n < nv) ? *(const float4*)(rp)     : z;
                pf[j*2+1] = (n < nv) ? *(const float4*)(rp + 4) : z;
            }
        }

        // ---- q projection + fused row-norm & ks_sum-dot partials
        {
            float pc[4][4];
            #pragma unroll
            for (int t = 0; t < 4; t++) { pc[t][0]=0.f; pc[t][1]=0.f; pc[t][2]=0.f; pc[t][3]=0.f; }
            #pragma unroll 4
            for (int kb = 0; kb < 32; kb++) {
                const float* xr = xsA + (ps * 16 + gq) * XS + kb * 8 + ct;
                uint4 a;
                a.x = fu(xr[0]); a.y = fu(xr[8 * XS]);
                a.z = fu(xr[4]); a.w = fu(xr[8 * XS + 4]);
                #pragma unroll
                for (int t = 0; t < 4; t++) {
                    int nt = nh * 4 + t;
                    const float* wp = wt + (kb * 8 + ct) * 64 + ((nt * 8 + gq) ^ (8 * ct));
                    uint2 b; b.x = fu(wp[0]); b.y = fu(wp[4 * 64]);
                    mma8(pc[t], a, b);
                }
            }
            int r0 = ps * 16 + gq;
            float nrm0 = 0.f, nrm1 = 0.f, dot0 = 0.f, dot1 = 0.f;
            #pragma unroll
            for (int t = 0; t < 4; t++) {
                int cb = (nh * 4 + t) * 8 + 2 * ct;
                float b0 = bias[cb], b1 = bias[cb + 1];
                float k0 = kss[cb],  k1 = kss[cb + 1];
                float v0 = pc[t][0] + b0, v1 = pc[t][1] + b1;
                float v2 = pc[t][2] + b0, v3 = pc[t][3] + b1;
                *(float2*)(qs + r0 * QS + cb)       = make_float2(v0, v1);
                *(float2*)(qs + (r0 + 8) * QS + cb) = make_float2(v2, v3);
                nrm0 += v0 * v0 + v1 * v1;  dot0 += v0 * k0 + v1 * k1;
                nrm1 += v2 * v2 + v3 * v3;  dot1 += v2 * k0 + v3 * k1;
            }
            nrm0 += __shfl_xor_sync(0xffffffffu, nrm0, 1);
            nrm0 += __shfl_xor_sync(0xffffffffu, nrm0, 2);
            nrm1 += __shfl_xor_sync(0xffffffffu, nrm1, 1);
            nrm1 += __shfl_xor_sync(0xffffffffu, nrm1, 2);
            dot0 += __shfl_xor_sync(0xffffffffu, dot0, 1);
            dot0 += __shfl_xor_sync(0xffffffffu, dot0, 2);
            dot1 += __shfl_xor_sync(0xffffffffu, dot1, 1);
            dot1 += __shfl_xor_sync(0xffffffffu, dot1, 2);
            if (ct == 0) {
                red [r0 * 2 + nh] = nrm0;  red [(r0 + 8) * 2 + nh] = nrm1;
                red2[r0 * 2 + nh] = dot0;  red2[(r0 + 8) * 2 + nh] = dot1;
            }
        }
        __syncthreads();

        if (tid < 64) {
            float s = red [tid * 2] + red [tid * 2 + 1];
            float d = red2[tid * 2] + red2[tid * 2 + 1];
            float iv = rsqrtf(s);
            inv[tid] = iv;
            rno[tid] = 1.0f / (iv * d + (float)NNODES);
        }
        __syncthreads();

        // ---- out = (qs_norm @ kvs + colsum) * rno  (normalization folded)
        {
            float oc[2][8][4];
            #pragma unroll
            for (int mi = 0; mi < 2; mi++)
                #pragma unroll
                for (int t = 0; t < 8; t++) {
                    oc[mi][t][0]=0.f; oc[mi][t][1]=0.f; oc[mi][t][2]=0.f; oc[mi][t][3]=0.f;
                }
            int nbase = sn * 32 + gq;
            float iv0 = inv[nbase], iv1 = inv[nbase + 8];
            float iv2 = inv[nbase + 16], iv3 = inv[nbase + 24];
            #pragma unroll
            for (int kb = 0; kb < 8; kb++) {
                uint4 a0, a1;
                {
                    const float* ap = qs + nbase * QS + kb * 8 + ct;
                    a0.x = fu(rna(ap[0] * iv0));          a0.y = fu(rna(ap[8 * QS] * iv1));
                    a0.z = fu(rna(ap[4] * iv0));          a0.w = fu(rna(ap[8 * QS + 4] * iv1));
                    const float* ap1 = ap + 16 * QS;
                    a1.x = fu(rna(ap1[0] * iv2));         a1.y = fu(rna(ap1[8 * QS] * iv3));
                    a1.z = fu(rna(ap1[4] * iv2));         a1.w = fu(rna(ap1[8 * QS + 4] * iv3));
                }
                const float* kp0 = kvs + (kb * 8 + ct) * 256;
                const float* kp1 = kvs + (kb * 8 + ct + 4) * 256;
                const int sw = 8 * ct;
                #pragma unroll
                for (int t = 0; t < 8; t++) {
                    int c = cq * 64 + t * 8 + gq;
                    uint2 b; b.x = fu(kp0[c ^ sw]); b.y = fu(kp1[c ^ sw]);
                    mma8(oc[0][t], a0, b);
                    mma8(oc[1][t], a1, b);
                }
            }
            #pragma unroll
            for (int mi = 0; mi < 2; mi++) {
                int n0 = sn * 32 + mi * 16 + gq;
                float r0v = rno[n0], r1v = rno[n0 + 8];
                #pragma unroll
                for (int t = 0; t < 8; t++) {
                    int c0 = cq * 64 + t * 8 + 2 * ct;
                    float cv0 = cs[c0], cv1 = cs[c0 + 1];
                    if (n0 < valid)
                        *(float2*)(out + (size_t)(base + n0) * (NHEADS * CIN) + h * CIN + c0) =
                            make_float2((oc[mi][t][0] + cv0) * r0v, (oc[mi][t][1] + cv1) * r0v);
                    if (n0 + 8 < valid)
                        *(float2*)(out + (size_t)(base + n0 + 8) * (NHEADS * CIN) + h * CIN + c0) =
                            make_float2((oc[mi][t][2] + cv0) * r1v, (oc[mi][t][3] + cv1) * r1v);
                }
            }
        }
        __syncthreads();
    }
}

// =====================================================================
extern "C" void kernel_launch(void* const* d_in, const int* in_sizes, int n_in,
                              void* d_out, int out_size)
{
    const float* x    = (const float*)d_in[0];
    const float* Wq_w = (const float*)d_in[1];
    const float* Wq_b = (const float*)d_in[2];
    const float* Wk_w = (const float*)d_in[3];
    const float* Wk_b = (const float*)d_in[4];
    float* out = (float*)d_out;

    const int smemA = 55744 * (int)sizeof(float);   // 222976 B
    const int smemB = 54528 * (int)sizeof(float);   // 218112 B

    cudaFuncSetAttribute(phaseA_kernel, cudaFuncAttributeMaxDynamicSharedMemorySize, smemA);
    cudaFuncSetAttribute(phaseB_kernel, cudaFuncAttributeMaxDynamicSharedMemorySize, smemB);

    phaseA_kernel<<<dim3(BPH, NHEADS), NTHR, smemA>>>(x, Wk_w, Wk_b);
    reduce_kernel<<<256, 256>>>();
    phaseB_kernel<<<dim3(BPH, NHEADS), NTHR, smemB>>>(x, Wq_w, Wq_b, out);
}

// round 13
// speedup vs baseline: 1.0741x; 1.0394x over previous
#include <cuda_runtime.h>
#include <math.h>
#include <stdint.h>

#define NNODES 100000
#define CIN    256
#define NHEADS 4
#define DHEAD  64
#define BPH    37
#define TILE   64
#define NT     ((NNODES + TILE - 1) / TILE)   // 1563
#define XS     260                            // xsA stride (A-frag clean)
#define KS     72                             // ks stride  (transposed-A clean)
#define QS     68                             // qs stride  (A-frag clean)
#define NTHR   256

// ---------------- helpers ----------------
__device__ __forceinline__ float rna(float f) {
    unsigned int u;
    asm("cvt.rna.tf32.f32 %0, %1;" : "=r"(u) : "f"(f));
    return __uint_as_float(u);
}
__device__ __forceinline__ unsigned int fu(float f) { return __float_as_uint(f); }
__device__ __forceinline__ void mma8(float c[4], uint4 a, uint2 b) {
    asm volatile("mma.sync.aligned.m16n8k8.row.col.f32.tf32.tf32.f32 "
        "{%0,%1,%2,%3}, {%4,%5,%6,%7}, {%8,%9}, {%0,%1,%2,%3};"
        : "+f"(c[0]), "+f"(c[1]), "+f"(c[2]), "+f"(c[3])
        : "r"(a.x), "r"(a.y), "r"(a.z), "r"(a.w), "r"(b.x), "r"(b.y));
}

// ---------------- device scratch ----------------
__device__ float g_part_kvs[BPH][NHEADS * DHEAD * CIN];
__device__ float g_part_kss[BPH][NHEADS * DHEAD];
__device__ float g_part_cs [BPH][CIN];
__device__ float g_kvs   [NHEADS * DHEAD * CIN];
__device__ float g_kssum [NHEADS * DHEAD];
__device__ float g_colsum[CIN];

extern __shared__ float smf[];

// =====================================================================
// Phase A  (== R12: pf[8] + folded normalize; 269us measured)
// smem floats: xsA 16640 | xsB 16384 | wt 16384 | ks 4608 | bias 64 |
//   kss 64 | red 512 | inv 64 | csred 1024 = 55744 (222976 B)
// =====================================================================
__global__ __launch_bounds__(NTHR, 1)
void phaseA_kernel(const float* __restrict__ x,
                   const float* __restrict__ Wk,
                   const float* __restrict__ bk)
{
    const int h = blockIdx.y, bx = blockIdx.x, tid = threadIdx.x;
    const int lane = tid & 31, w = tid >> 5;
    const int gq = lane >> 2, ct = lane & 3;

    float* xsA  = smf;             // [64][260]
    float* xsB  = xsA + 16640;     // [64][256] swizzled: phys_c = c ^ (8*(n&3))
    float* wt   = xsB + 16384;     // [256][64] swizzled: phys_m = m ^ (8*(c&3))
    float* ks   = wt  + 16384;     // [64][KS] raw (bias added, NOT normalized)
    float* bias = ks  + 4608;
    float* kss  = bias + 64;
    float* red  = kss + 64;        // [512]
    float* inv  = red + 512;       // [64]
    float* csred= inv + 64;        // [256][4]

    for (int i = tid; i < 16384; i += NTHR) {
        int c = i >> 6, m = i & 63;
        wt[c * 64 + (m ^ (8 * (c & 3)))] = rna(Wk[(h * 64 + m) * 256 + c]);
    }
    if (tid < 64) { bias[tid] = bk[h * 64 + tid]; kss[tid] = 0.f; }

    const int ps = w >> 1, nh = w & 1;   // proj: 4 row-slabs x 2 col-halves
    const int km = w >> 2, cq = w & 3;   // kv:   2 m-slabs(32) x 4 c-quarters(64)

    float kvC[2][8][4];
    #pragma unroll
    for (int mi = 0; mi < 2; mi++)
        #pragma unroll
        for (int t = 0; t < 8; t++) {
            kvC[mi][t][0]=0.f; kvC[mi][t][1]=0.f; kvC[mi][t][2]=0.f; kvC[mi][t][3]=0.f;
        }
    float4 csacc = make_float4(0.f, 0.f, 0.f, 0.f);

    float4 pf[8];
    {
        const int base = bx * TILE;
        const int valid = (NNODES - base < TILE) ? (NNODES - base) : TILE;
        #pragma unroll
        for (int j = 0; j < 8; j++) {
            int i = tid + j * NTHR;
            int n = i >> 6, c4 = (i & 63) << 2;
            pf[j] = (n < valid) ? *(const float4*)(x + (size_t)(base + n) * CIN + c4)
                                : make_float4(0.f, 0.f, 0.f, 0.f);
        }
    }
    __syncthreads();

    for (int tile = bx; tile < NT; tile += BPH) {
        const int base = tile * TILE;
        const int valid = (NNODES - base < TILE) ? (NNODES - base) : TILE;

        #pragma unroll
        for (int j = 0; j < 8; j++) {
            int i = tid + j * NTHR;
            int n = i >> 6, c4 = (i & 63) << 2;
            float4 v = pf[j];
            csacc.x += v.x; csacc.y += v.y; csacc.z += v.z; csacc.w += v.w;
            float4 r = make_float4(rna(v.x), rna(v.y), rna(v.z), rna(v.w));
            *(float4*)(xsA + n * XS + c4) = r;
            *(float4*)(xsB + n * 256 + (c4 ^ (8 * (n & 3)))) = r;
        }
        #pragma unroll
        for (int j = 8; j < 16; j++) {
            int i = tid + j * NTHR;
            int n = i >> 6, c4 = (i & 63) << 2;
            float4 v = (n < valid) ? *(const float4*)(x + (size_t)(base + n) * CIN + c4)
                                   : make_float4(0.f, 0.f, 0.f, 0.f);
            csacc.x += v.x; csacc.y += v.y; csacc.z += v.z; csacc.w += v.w;
            float4 r = make_float4(rna(v.x), rna(v.y), rna(v.z), rna(v.w));
            *(float4*)(xsA + n * XS + c4) = r;
            *(float4*)(xsB + n * 256 + (c4 ^ (8 * (n & 3)))) = r;
        }
        __syncthreads();

        if (tile + BPH < NT) {
            const int nb = (tile + BPH) * TILE;
            const int nv = (NNODES - nb < TILE) ? (NNODES - nb) : TILE;
            #pragma unroll
            for (int j = 0; j < 8; j++) {
                int i = tid + j * NTHR;
                int n = i >> 6, c4 = (i & 63) << 2;
                pf[j] = (n < nv) ? *(const float4*)(x + (size_t)(nb + n) * CIN + c4)
                                 : make_float4(0.f, 0.f, 0.f, 0.f);
            }
        }

        // ---- k projection + fused row-norm partials
        {
            float pc[4][4];
            #pragma unroll
            for (int t = 0; t < 4; t++) { pc[t][0]=0.f; pc[t][1]=0.f; pc[t][2]=0.f; pc[t][3]=0.f; }
            #pragma unroll 4
            for (int kb = 0; kb < 32; kb++) {
                const float* xr = xsA + (ps * 16 + gq) * XS + kb * 8 + ct;
                uint4 a;
                a.x = fu(xr[0]); a.y = fu(xr[8 * XS]);
                a.z = fu(xr[4]); a.w = fu(xr[8 * XS + 4]);
                #pragma unroll
                for (int t = 0; t < 4; t++) {
                    int nt = nh * 4 + t;
                    const float* wp = wt + (kb * 8 + ct) * 64 + ((nt * 8 + gq) ^ (8 * ct));
                    uint2 b; b.x = fu(wp[0]); b.y = fu(wp[4 * 64]);
                    mma8(pc[t], a, b);
                }
            }
            int r0 = ps * 16 + gq;
            float nrm0 = 0.f, nrm1 = 0.f;
            #pragma unroll
            for (int t = 0; t < 4; t++) {
                int cb = (nh * 4 + t) * 8 + 2 * ct;
                float b0 = bias[cb], b1 = bias[cb + 1];
                float v0 = pc[t][0] + b0, v1 = pc[t][1] + b1;
                float v2 = pc[t][2] + b0, v3 = pc[t][3] + b1;
                *(float2*)(ks + r0 * KS + cb)       = make_float2(v0, v1);
                *(float2*)(ks + (r0 + 8) * KS + cb) = make_float2(v2, v3);
                nrm0 += v0 * v0 + v1 * v1;
                nrm1 += v2 * v2 + v3 * v3;
            }
            nrm0 += __shfl_xor_sync(0xffffffffu, nrm0, 1);
            nrm0 += __shfl_xor_sync(0xffffffffu, nrm0, 2);
            nrm1 += __shfl_xor_sync(0xffffffffu, nrm1, 1);
            nrm1 += __shfl_xor_sync(0xffffffffu, nrm1, 2);
            if (ct == 0) {
                red[r0 * 2 + nh]       = nrm0;
                red[(r0 + 8) * 2 + nh] = nrm1;
            }
        }
        __syncthreads();

        if (tid < 64) {
            float s = red[tid * 2] + red[tid * 2 + 1];
            inv[tid] = (tid < valid) ? rsqrtf(s) : 0.f;
        }
        __syncthreads();

        // ---- ks_sum partials from raw ks (normalize folded)
        {
            int m = tid & 63, rg = tid >> 6;
            float s = 0.f;
            #pragma unroll
            for (int r = 0; r < 16; r++) {
                int n = rg * 16 + r;
                s += rna(ks[n * KS + m] * inv[n]);
            }
            red[rg * 64 + m] = s;
        }
        __syncthreads();
        if (tid < 64)
            kss[tid] += red[tid] + red[64 + tid] + red[128 + tid] + red[192 + tid];

        // ---- kv += ks^T @ x  (normalization folded into A-frags)
        {
            #pragma unroll
            for (int kb = 0; kb < 8; kb++) {
                int n0 = kb * 8 + ct;
                float iv0 = inv[n0], iv1 = inv[n0 + 4];
                uint4 a0, a1;
                {
                    const float* kp = ks + n0 * KS + km * 32 + gq;
                    a0.x = fu(rna(kp[0]  * iv0));          a0.y = fu(rna(kp[8]  * iv0));
                    a0.z = fu(rna(kp[4 * KS] * iv1));      a0.w = fu(rna(kp[4 * KS + 8] * iv1));
                    a1.x = fu(rna(kp[16] * iv0));          a1.y = fu(rna(kp[24] * iv0));
                    a1.z = fu(rna(kp[4 * KS + 16] * iv1)); a1.w = fu(rna(kp[4 * KS + 24] * iv1));
                }
                const float* xb0 = xsB + n0 * 256;
                const float* xb1 = xsB + (n0 + 4) * 256;
                const int sw = 8 * ct;
                #pragma unroll
                for (int t = 0; t < 8; t++) {
                    int c = cq * 64 + t * 8 + gq;
                    uint2 b; b.x = fu(xb0[c ^ sw]); b.y = fu(xb1[c ^ sw]);
                    mma8(kvC[0][t], a0, b);
                    mma8(kvC[1][t], a1, b);
                }
            }
        }
        __syncthreads();
    }

    {
        float* dst = g_part_kvs[bx] + h * (DHEAD * CIN);
        #pragma unroll
        for (int mi = 0; mi < 2; mi++)
            #pragma unroll
            for (int t = 0; t < 8; t++) {
                int c0 = cq * 64 + t * 8 + 2 * ct;
                int m0 = km * 32 + mi * 16 + gq;
                dst[m0 * 256 + c0]           = kvC[mi][t][0];
                dst[m0 * 256 + c0 + 1]       = kvC[mi][t][1];
                dst[(m0 + 8) * 256 + c0]     = kvC[mi][t][2];
                dst[(m0 + 8) * 256 + c0 + 1] = kvC[mi][t][3];
            }
    }
    if (tid < 64) g_part_kss[bx][h * 64 + tid] = kss[tid];
    {
        int c4 = (tid & 63) * 4, grp = tid >> 6;
        csred[(c4+0)*4+grp] = csacc.x; csred[(c4+1)*4+grp] = csacc.y;
        csred[(c4+2)*4+grp] = csacc.z; csred[(c4+3)*4+grp] = csacc.w;
    }
    __syncthreads();
    if (h == 0)
        g_part_cs[bx][tid] = csred[tid*4] + csred[tid*4+1] + csred[tid*4+2] + csred[tid*4+3];
}

// =====================================================================
// Reduce
// =====================================================================
__global__ void reduce_kernel()
{
    int i = blockIdx.x * 256 + threadIdx.x;
    if (i < NHEADS * DHEAD * CIN) {
        float s = 0.f;
        #pragma unroll 1
        for (int b = 0; b < BPH; b++) s += g_part_kvs[b][i];
        g_kvs[i] = s;
    }
    if (i < NHEADS * DHEAD) {
        float s = 0.f;
        for (int b = 0; b < BPH; b++) s += g_part_kss[b][i];
        g_kssum[i] = s;
    }
    if (i < CIN) {
        float s = 0.f;
        for (int b = 0; b < BPH; b++) s += g_part_cs[b][i];
        g_colsum[i] = s;
    }
}

// =====================================================================
// Phase B  (pf[16] full prefetch + folded normalize in out-GEMM)
// smem floats: xsA 16640 | wt 16384 | kvs 16384 | qs 4352 | bias 64 |
//   kss 64 | cs 256 | red 128 | red2 128 | inv 64 | rno 64 = 54528 (218112 B)
// =====================================================================
__global__ __launch_bounds__(NTHR, 1)
void phaseB_kernel(const float* __restrict__ x,
                   const float* __restrict__ Wq,
                   const float* __restrict__ bq,
                   float* __restrict__ out)
{
    const int h = blockIdx.y, tid = threadIdx.x;
    const int lane = tid & 31, w = tid >> 5;
    const int gq = lane >> 2, ct = lane & 3;

    float* xsA  = smf;             // [64][260]
    float* wt   = xsA + 16640;     // [256][64] swizzled
    float* kvs  = wt  + 16384;     // [64][256] swizzled: phys_c = c ^ (8*(m&3))
    float* qs   = kvs + 16384;     // [64][QS] raw (bias added, NOT normalized)
    float* bias = qs  + 4352;
    float* kss  = bias + 64;
    float* cs   = kss + 64;
    float* red  = cs  + 256;       // [128]
    float* red2 = red + 128;       // [128]
    float* inv  = red2 + 128;      // [64]
    float* rno  = inv + 64;        // [64]

    for (int i = tid; i < 16384; i += NTHR) {
        int c = i >> 6, m = i & 63;
        wt[c * 64 + (m ^ (8 * (c & 3)))] = rna(Wq[(h * 64 + m) * 256 + c]);
    }
    for (int i = tid; i < 16384; i += NTHR) {
        int m = i >> 8, c = i & 255;
        kvs[m * 256 + (c ^ (8 * (m & 3)))] = rna(g_kvs[h * 16384 + m * 256 + c]);
    }
    if (tid < 64) { bias[tid] = bq[h * 64 + tid]; kss[tid] = g_kssum[h * 64 + tid]; }
    cs[tid] = g_colsum[tid];

    const int ps = w >> 1, nh = w & 1;   // proj
    const int sn = w >> 2, cq = w & 3;   // out: 2 row-slabs(32) x 4 c-quarters(64)

    float4 pf[16];
    {
        const int base = blockIdx.x * TILE;
        const int valid = (NNODES - base < TILE) ? (NNODES - base) : TILE;
        #pragma unroll
        for (int j = 0; j < 8; j++) {
            int s = tid + j * 256;
            int n = s >> 5, c8 = (s & 31) * 8;
            const float* rp = x + (size_t)(base + n) * CIN + c8;
            float4 z = make_float4(0.f,0.f,0.f,0.f);
            pf[j*2+0] = (n < valid) ? *(const float4*)(rp)     : z;
            pf[j*2+1] = (n < valid) ? *(const float4*)(rp + 4) : z;
        }
    }
    __syncthreads();

    for (int tile = blockIdx.x; tile < NT; tile += BPH) {
        const int base = tile * TILE;
        const int valid = (NNODES - base < TILE) ? (NNODES - base) : TILE;

        #pragma unroll
        for (int j = 0; j < 8; j++) {
            int s = tid + j * 256;
            int n = s >> 5, c8g = s & 31;
            float4 v0 = pf[j*2+0], v1 = pf[j*2+1];
            float* a0 = xsA + n * XS + c8g * 8;
            *(float4*)(a0)     = make_float4(rna(v0.x), rna(v0.y), rna(v0.z), rna(v0.w));
            *(float4*)(a0 + 4) = make_float4(rna(v1.x), rna(v1.y), rna(v1.z), rna(v1.w));
        }
        __syncthreads();

        if (tile + BPH < NT) {
            const int nb = (tile + BPH) * TILE;
            const int nv = (NNODES - nb < TILE) ? (NNODES - nb) : TILE;
            #pragma unroll
            for (int j = 0; j < 8; j++) {
                int s = tid + j * 256;
                int n = s >> 5, c8 = (s & 31) * 8;
                const float* rp = x + (size_t)(nb + n) * CIN + c8;
                float4 z = make_float4(0.f,0.f,0.f,0.f);
                pf[j*2+0] = (n < nv) ? *(const float4*)(rp)     : z;
                pf[j*2+1] = (n < nv) ? *(const float4*)(rp + 4) : z;
            }
        }

        // ---- q projection + fused row-norm & ks_sum-dot partials
        {
            float pc[4][4];
            #pragma unroll
            for (int t = 0; t < 4; t++) { pc[t][0]=0.f; pc[t][1]=0.f; pc[t][2]=0.f; pc[t][3]=0.f; }
            #pragma unroll 4
            for (int kb = 0; kb < 32; kb++) {
                const float* xr = xsA + (ps * 16 + gq) * XS + kb * 8 + ct;
                uint4 a;
                a.x = fu(xr[0]); a.y = fu(xr[8 * XS]);
                a.z = fu(xr[4]); a.w = fu(xr[8 * XS + 4]);
                #pragma unroll
                for (int t = 0; t < 4; t++) {
                    int nt = nh * 4 + t;
                    const float* wp = wt + (kb * 8 + ct) * 64 + ((nt * 8 + gq) ^ (8 * ct));
                    uint2 b; b.x = fu(wp[0]); b.y = fu(wp[4 * 64]);
                    mma8(pc[t], a, b);
                }
            }
            int r0 = ps * 16 + gq;
            float nrm0 = 0.f, nrm1 = 0.f, dot0 = 0.f, dot1 = 0.f;
            #pragma unroll
            for (int t = 0; t < 4; t++) {
                int cb = (nh * 4 + t) * 8 + 2 * ct;
                float b0 = bias[cb], b1 = bias[cb + 1];
                float k0 = kss[cb],  k1 = kss[cb + 1];
                float v0 = pc[t][0] + b0, v1 = pc[t][1] + b1;
                float v2 = pc[t][2] + b0, v3 = pc[t][3] + b1;
                *(float2*)(qs + r0 * QS + cb)       = make_float2(v0, v1);
                *(float2*)(qs + (r0 + 8) * QS + cb) = make_float2(v2, v3);
                nrm0 += v0 * v0 + v1 * v1;  dot0 += v0 * k0 + v1 * k1;
                nrm1 += v2 * v2 + v3 * v3;  dot1 += v2 * k0 + v3 * k1;
            }
            nrm0 += __shfl_xor_sync(0xffffffffu, nrm0, 1);
            nrm0 += __shfl_xor_sync(0xffffffffu, nrm0, 2);
            nrm1 += __shfl_xor_sync(0xffffffffu, nrm1, 1);
            nrm1 += __shfl_xor_sync(0xffffffffu, nrm1, 2);
            dot0 += __shfl_xor_sync(0xffffffffu, dot0, 1);
            dot0 += __shfl_xor_sync(0xffffffffu, dot0, 2);
            dot1 += __shfl_xor_sync(0xffffffffu, dot1, 1);
            dot1 += __shfl_xor_sync(0xffffffffu, dot1, 2);
            if (ct == 0) {
                red [r0 * 2 + nh] = nrm0;  red [(r0 + 8) * 2 + nh] = nrm1;
                red2[r0 * 2 + nh] = dot0;  red2[(r0 + 8) * 2 + nh] = dot1;
            }
        }
        __syncthreads();

        if (tid < 64) {
            float s = red [tid * 2] + red [tid * 2 + 1];
            float d = red2[tid * 2] + red2[tid * 2 + 1];
            float iv = rsqrtf(s);
            inv[tid] = iv;
            rno[tid] = 1.0f / (iv * d + (float)NNODES);
        }
        __syncthreads();

        // ---- out = (qs_norm @ kvs + colsum) * rno  (normalization folded)
        {
            float oc[2][8][4];
            #pragma unroll
            for (int mi = 0; mi < 2; mi++)
                #pragma unroll
                for (int t = 0; t < 8; t++) {
                    oc[mi][t][0]=0.f; oc[mi][t][1]=0.f; oc[mi][t][2]=0.f; oc[mi][t][3]=0.f;
                }
            int nbase = sn * 32 + gq;
            float iv0 = inv[nbase], iv1 = inv[nbase + 8];
            float iv2 = inv[nbase + 16], iv3 = inv[nbase + 24];
            #pragma unroll
            for (int kb = 0; kb < 8; kb++) {
                uint4 a0, a1;
                {
                    const float* ap = qs + nbase * QS + kb * 8 + ct;
                    a0.x = fu(rna(ap[0] * iv0));          a0.y = fu(rna(ap[8 * QS] * iv1));
                    a0.z = fu(rna(ap[4] * iv0));          a0.w = fu(rna(ap[8 * QS + 4] * iv1));
                    const float* ap1 = ap + 16 * QS;
                    a1.x = fu(rna(ap1[0] * iv2));         a1.y = fu(rna(ap1[8 * QS] * iv3));
                    a1.z = fu(rna(ap1[4] * iv2));         a1.w = fu(rna(ap1[8 * QS + 4] * iv3));
                }
                const float* kp0 = kvs + (kb * 8 + ct) * 256;
                const float* kp1 = kvs + (kb * 8 + ct + 4) * 256;
                const int sw = 8 * ct;
                #pragma unroll
                for (int t = 0; t < 8; t++) {
                    int c = cq * 64 + t * 8 + gq;
                    uint2 b; b.x = fu(kp0[c ^ sw]); b.y = fu(kp1[c ^ sw]);
                    mma8(oc[0][t], a0, b);
                    mma8(oc[1][t], a1, b);
                }
            }
            #pragma unroll
            for (int mi = 0; mi < 2; mi++) {
                int n0 = sn * 32 + mi * 16 + gq;
                float r0v = rno[n0], r1v = rno[n0 + 8];
                #pragma unroll
                for (int t = 0; t < 8; t++) {
                    int c0 = cq * 64 + t * 8 + 2 * ct;
                    float cv0 = cs[c0], cv1 = cs[c0 + 1];
                    if (n0 < valid)
                        *(float2*)(out + (size_t)(base + n0) * (NHEADS * CIN) + h * CIN + c0) =
                            make_float2((oc[mi][t][0] + cv0) * r0v, (oc[mi][t][1] + cv1) * r0v);
                    if (n0 + 8 < valid)
                        *(float2*)(out + (size_t)(base + n0 + 8) * (NHEADS * CIN) + h * CIN + c0) =
                            make_float2((oc[mi][t][2] + cv0) * r1v, (oc[mi][t][3] + cv1) * r1v);
                }
            }
        }
        __syncthreads();
    }
}

// =====================================================================
extern "C" void kernel_launch(void* const* d_in, const int* in_sizes, int n_in,
                              void* d_out, int out_size)
{
    const float* x    = (const float*)d_in[0];
    const float* Wq_w = (const float*)d_in[1];
    const float* Wq_b = (const float*)d_in[2];
    const float* Wk_w = (const float*)d_in[3];
    const float* Wk_b = (const float*)d_in[4];
    float* out = (float*)d_out;

    const int smemA = 55744 * (int)sizeof(float);   // 222976 B
    const int smemB = 54528 * (int)sizeof(float);   // 218112 B

    cudaFuncSetAttribute(phaseA_kernel, cudaFuncAttributeMaxDynamicSharedMemorySize, smemA);
    cudaFuncSetAttribute(phaseB_kernel, cudaFuncAttributeMaxDynamicSharedMemorySize, smemB);

    phaseA_kernel<<<dim3(BPH, NHEADS), NTHR, smemA>>>(x, Wk_w, Wk_b);
    reduce_kernel<<<256, 256>>>();
    phaseB_kernel<<<dim3(BPH, NHEADS), NTHR, smemB>>>(x, Wq_w, Wq_b, out);
}

// round 14
// speedup vs baseline: 1.2463x; 1.1602x over previous
#include <cuda_runtime.h>
#include <math.h>
#include <stdint.h>

#define NNODES 100000
#define CIN    256
#define NHEADS 4
#define DHEAD  64
#define BPH    37
#define BPHB   74
#define TILE   64
#define NT     ((NNODES + TILE - 1) / TILE)   // 1563
#define NPAD   (NT * TILE)                    // 100032
#define XS     260                            // xsA stride (A-frag clean)
#define KS     72                             // ks stride  (transposed-A clean)
#define QS     68                             // qn stride  (A-frag clean)
#define NTHR   256

// ---------------- helpers ----------------
__device__ __forceinline__ float rna(float f) {
    unsigned int u;
    asm("cvt.rna.tf32.f32 %0, %1;" : "=r"(u) : "f"(f));
    return __uint_as_float(u);
}
__device__ __forceinline__ unsigned int fu(float f) { return __float_as_uint(f); }
__device__ __forceinline__ void mma8(float c[4], uint4 a, uint2 b) {
    asm volatile("mma.sync.aligned.m16n8k8.row.col.f32.tf32.tf32.f32 "
        "{%0,%1,%2,%3}, {%4,%5,%6,%7}, {%8,%9}, {%0,%1,%2,%3};"
        : "+f"(c[0]), "+f"(c[1]), "+f"(c[2]), "+f"(c[3])
        : "r"(a.x), "r"(a.y), "r"(a.z), "r"(a.w), "r"(b.x), "r"(b.y));
}

// ---------------- device scratch ----------------
__device__ float g_qn[(size_t)NHEADS * NPAD * DHEAD];   // normalized q, fp32
__device__ float g_part_kvs[BPH][NHEADS * DHEAD * CIN];
__device__ float g_part_kss[BPH][NHEADS * DHEAD];
__device__ float g_part_cs [BPH][CIN];
__device__ float g_kvs   [NHEADS * DHEAD * CIN];
__device__ float g_kssum [NHEADS * DHEAD];
__device__ float g_colsum[CIN];

extern __shared__ float smf[];

// =====================================================================
// Phase A: k-proj + q-proj (shared A-frags) + normalize + kv + qn STG
// smem floats: xsA 16640 | wtk 16384 | wtq 16384 | ks 4608 | biask 64 |
//  biasq 64 | kss 64 | red 512 | redq 512 | inv 64 | qinv 64 | csred 1024
//  = 56384 (225536 B)
// =====================================================================
__global__ __launch_bounds__(NTHR, 1)
void phaseA_kernel(const float* __restrict__ x,
                   const float* __restrict__ Wk,
                   const float* __restrict__ bk,
                   const float* __restrict__ Wq,
                   const float* __restrict__ bq)
{
    const int h = blockIdx.y, bx = blockIdx.x, tid = threadIdx.x;
    const int lane = tid & 31, w = tid >> 5;
    const int gq = lane >> 2, ct = lane & 3;

    float* xsA   = smf;              // [64][260]
    float* wtk   = xsA + 16640;      // [256][64] swizzled: phys_m = m ^ (8*(c&3))
    float* wtq   = wtk + 16384;      // [256][64] swizzled
    float* ks    = wtq + 16384;      // [64][KS] raw (bias added, NOT normalized)
    float* biask = ks + 4608;
    float* biasq = biask + 64;
    float* kss   = biasq + 64;
    float* red   = kss + 64;         // [512]
    float* redq  = red + 512;        // [512]
    float* inv   = redq + 512;       // [64]
    float* qinv  = inv + 64;         // [64]
    float* csred = qinv + 64;        // [256][4]

    for (int i = tid; i < 16384; i += NTHR) {
        int c = i >> 6, m = i & 63;
        int sm = m ^ (8 * (c & 3));
        wtk[c * 64 + sm] = rna(Wk[(h * 64 + m) * 256 + c]);
        wtq[c * 64 + sm] = rna(Wq[(h * 64 + m) * 256 + c]);
    }
    if (tid < 64) { biask[tid] = bk[h * 64 + tid]; biasq[tid] = bq[h * 64 + tid]; kss[tid] = 0.f; }

    const int ps = w >> 1, nh = w & 1;   // proj: 4 row-slabs x 2 col-halves
    const int km = w >> 2, cq = w & 3;   // kv:   2 m-slabs(32) x 4 c-quarters(64)

    float kvC[2][8][4];
    #pragma unroll
    for (int mi = 0; mi < 2; mi++)
        #pragma unroll
        for (int t = 0; t < 8; t++) {
            kvC[mi][t][0]=0.f; kvC[mi][t][1]=0.f; kvC[mi][t][2]=0.f; kvC[mi][t][3]=0.f;
        }
    float4 csacc = make_float4(0.f, 0.f, 0.f, 0.f);

    float4 pf[8];
    {
        const int base = bx * TILE;
        const int valid = (NNODES - base < TILE) ? (NNODES - base) : TILE;
        #pragma unroll
        for (int j = 0; j < 8; j++) {
            int i = tid + j * NTHR;
            int n = i >> 6, c4 = (i & 63) << 2;
            pf[j] = (n < valid) ? *(const float4*)(x + (size_t)(base + n) * CIN + c4)
                                : make_float4(0.f, 0.f, 0.f, 0.f);
        }
    }
    __syncthreads();

    for (int tile = bx; tile < NT; tile += BPH) {
        const int base = tile * TILE;
        const int valid = (NNODES - base < TILE) ? (NNODES - base) : TILE;

        // ---- store tile (xsA only) + colsum partials
        #pragma unroll
        for (int j = 0; j < 8; j++) {
            int i = tid + j * NTHR;
            int n = i >> 6, c4 = (i & 63) << 2;
            float4 v = pf[j];
            csacc.x += v.x; csacc.y += v.y; csacc.z += v.z; csacc.w += v.w;
            *(float4*)(xsA + n * XS + c4) =
                make_float4(rna(v.x), rna(v.y), rna(v.z), rna(v.w));
        }
        #pragma unroll
        for (int j = 8; j < 16; j++) {
            int i = tid + j * NTHR;
            int n = i >> 6, c4 = (i & 63) << 2;
            float4 v = (n < valid) ? *(const float4*)(x + (size_t)(base + n) * CIN + c4)
                                   : make_float4(0.f, 0.f, 0.f, 0.f);
            csacc.x += v.x; csacc.y += v.y; csacc.z += v.z; csacc.w += v.w;
            *(float4*)(xsA + n * XS + c4) =
                make_float4(rna(v.x), rna(v.y), rna(v.z), rna(v.w));
        }
        __syncthreads();

        if (tile + BPH < NT) {
            const int nb = (tile + BPH) * TILE;
            const int nv = (NNODES - nb < TILE) ? (NNODES - nb) : TILE;
            #pragma unroll
            for (int j = 0; j < 8; j++) {
                int i = tid + j * NTHR;
                int n = i >> 6, c4 = (i & 63) << 2;
                pf[j] = (n < nv) ? *(const float4*)(x + (size_t)(nb + n) * CIN + c4)
                                 : make_float4(0.f, 0.f, 0.f, 0.f);
            }
        }

        // ---- fused k-proj + q-proj (shared a-frags) + fused norm partials
        float qc[4][4];
        {
            float pc[4][4];
            #pragma unroll
            for (int t = 0; t < 4; t++) {
                pc[t][0]=0.f; pc[t][1]=0.f; pc[t][2]=0.f; pc[t][3]=0.f;
                qc[t][0]=0.f; qc[t][1]=0.f; qc[t][2]=0.f; qc[t][3]=0.f;
            }
            #pragma unroll 2
            for (int kb = 0; kb < 32; kb++) {
                const float* xr = xsA + (ps * 16 + gq) * XS + kb * 8 + ct;
                uint4 a;
                a.x = fu(xr[0]); a.y = fu(xr[8 * XS]);
                a.z = fu(xr[4]); a.w = fu(xr[8 * XS + 4]);
                #pragma unroll
                for (int t = 0; t < 4; t++) {
                    int off = (kb * 8 + ct) * 64 + (((nh * 4 + t) * 8 + gq) ^ (8 * ct));
                    uint2 b;
                    b.x = fu(wtk[off]); b.y = fu(wtk[off + 4 * 64]);
                    mma8(pc[t], a, b);
                    uint2 bq2;
                    bq2.x = fu(wtq[off]); bq2.y = fu(wtq[off + 4 * 64]);
                    mma8(qc[t], a, bq2);
                }
            }
            int r0 = ps * 16 + gq;
            float nrm0 = 0.f, nrm1 = 0.f, qn0 = 0.f, qn1 = 0.f;
            #pragma unroll
            for (int t = 0; t < 4; t++) {
                int cb = (nh * 4 + t) * 8 + 2 * ct;
                float bk0 = biask[cb], bk1 = biask[cb + 1];
                float bq0 = biasq[cb], bq1 = biasq[cb + 1];
                float v0 = pc[t][0] + bk0, v1 = pc[t][1] + bk1;
                float v2 = pc[t][2] + bk0, v3 = pc[t][3] + bk1;
                *(float2*)(ks + r0 * KS + cb)       = make_float2(v0, v1);
                *(float2*)(ks + (r0 + 8) * KS + cb) = make_float2(v2, v3);
                nrm0 += v0 * v0 + v1 * v1;
                nrm1 += v2 * v2 + v3 * v3;
                qc[t][0] += bq0; qc[t][1] += bq1;
                qc[t][2] += bq0; qc[t][3] += bq1;
                qn0 += qc[t][0] * qc[t][0] + qc[t][1] * qc[t][1];
                qn1 += qc[t][2] * qc[t][2] + qc[t][3] * qc[t][3];
            }
            nrm0 += __shfl_xor_sync(0xffffffffu, nrm0, 1);
            nrm0 += __shfl_xor_sync(0xffffffffu, nrm0, 2);
            nrm1 += __shfl_xor_sync(0xffffffffu, nrm1, 1);
            nrm1 += __shfl_xor_sync(0xffffffffu, nrm1, 2);
            qn0 += __shfl_xor_sync(0xffffffffu, qn0, 1);
            qn0 += __shfl_xor_sync(0xffffffffu, qn0, 2);
            qn1 += __shfl_xor_sync(0xffffffffu, qn1, 1);
            qn1 += __shfl_xor_sync(0xffffffffu, qn1, 2);
            if (ct == 0) {
                red [r0 * 2 + nh] = nrm0;  red [(r0 + 8) * 2 + nh] = nrm1;
                redq[r0 * 2 + nh] = qn0;   redq[(r0 + 8) * 2 + nh] = qn1;
            }
        }
        __syncthreads();

        if (tid < 64) {
            float s = red[tid * 2] + red[tid * 2 + 1];
            inv[tid] = (tid < valid) ? rsqrtf(s) : 0.f;
        } else if (tid < 128) {
            int n = tid - 64;
            float s = redq[n * 2] + redq[n * 2 + 1];
            qinv[n] = (n < valid) ? rsqrtf(s) : 0.f;
        }
        __syncthreads();

        // ---- qn store to gmem (registers -> STG, no smem round trip)
        {
            int r0 = ps * 16 + gq;
            float iq0 = qinv[r0], iq1 = qinv[r0 + 8];
            float* q0 = g_qn + ((size_t)h * NPAD + base + r0) * DHEAD;
            float* q1 = g_qn + ((size_t)h * NPAD + base + r0 + 8) * DHEAD;
            #pragma unroll
            for (int t = 0; t < 4; t++) {
                int cb = (nh * 4 + t) * 8 + 2 * ct;
                *(float2*)(q0 + cb) = make_float2(qc[t][0] * iq0, qc[t][1] * iq0);
                *(float2*)(q1 + cb) = make_float2(qc[t][2] * iq1, qc[t][3] * iq1);
            }
        }

        // ---- ks_sum partials from raw ks (normalize folded)
        {
            int m = tid & 63, rg = tid >> 6;
            float s = 0.f;
            #pragma unroll
            for (int r = 0; r < 16; r++) {
                int n = rg * 16 + r;
                s += rna(ks[n * KS + m] * inv[n]);
            }
            red[rg * 64 + m] = s;
        }

        // ---- kv += ks^T @ x  (b-frags from xsA)
        {
            #pragma unroll
            for (int kb = 0; kb < 8; kb++) {
                int n0 = kb * 8 + ct;
                float iv0 = inv[n0], iv1 = inv[n0 + 4];
                uint4 a0, a1;
                {
                    const float* kp = ks + n0 * KS + km * 32 + gq;
                    a0.x = fu(rna(kp[0]  * iv0));          a0.y = fu(rna(kp[8]  * iv0));
                    a0.z = fu(rna(kp[4 * KS] * iv1));      a0.w = fu(rna(kp[4 * KS + 8] * iv1));
                    a1.x = fu(rna(kp[16] * iv0));          a1.y = fu(rna(kp[24] * iv0));
                    a1.z = fu(rna(kp[4 * KS + 16] * iv1)); a1.w = fu(rna(kp[4 * KS + 24] * iv1));
                }
                const float* xb0 = xsA + n0 * XS;
                const float* xb1 = xsA + (n0 + 4) * XS;
                #pragma unroll
                for (int t = 0; t < 8; t++) {
                    int c = cq * 64 + t * 8 + gq;
                    uint2 b; b.x = fu(xb0[c]); b.y = fu(xb1[c]);
                    mma8(kvC[0][t], a0, b);
                    mma8(kvC[1][t], a1, b);
                }
            }
        }
        __syncthreads();

        if (tid < 64)
            kss[tid] += red[tid] + red[64 + tid] + red[128 + tid] + red[192 + tid];
    }
    __syncthreads();

    {
        float* dst = g_part_kvs[bx] + h * (DHEAD * CIN);
        #pragma unroll
        for (int mi = 0; mi < 2; mi++)
            #pragma unroll
            for (int t = 0; t < 8; t++) {
                int c0 = cq * 64 + t * 8 + 2 * ct;
                int m0 = km * 32 + mi * 16 + gq;
                dst[m0 * 256 + c0]           = kvC[mi][t][0];
                dst[m0 * 256 + c0 + 1]       = kvC[mi][t][1];
                dst[(m0 + 8) * 256 + c0]     = kvC[mi][t][2];
                dst[(m0 + 8) * 256 + c0 + 1] = kvC[mi][t][3];
            }
    }
    if (tid < 64) g_part_kss[bx][h * 64 + tid] = kss[tid];
    {
        int c4 = (tid & 63) * 4, grp = tid >> 6;
        csred[(c4+0)*4+grp] = csacc.x; csred[(c4+1)*4+grp] = csacc.y;
        csred[(c4+2)*4+grp] = csacc.z; csred[(c4+3)*4+grp] = csacc.w;
    }
    __syncthreads();
    if (h == 0)
        g_part_cs[bx][tid] = csred[tid*4] + csred[tid*4+1] + csred[tid*4+2] + csred[tid*4+3];
}

// =====================================================================
// Reduce
// =====================================================================
__global__ void reduce_kernel()
{
    int i = blockIdx.x * 256 + threadIdx.x;
    if (i < NHEADS * DHEAD * CIN) {
        float s = 0.f;
        #pragma unroll 1
        for (int b = 0; b < BPH; b++) s += g_part_kvs[b][i];
        g_kvs[i] = s;
    }
    if (i < NHEADS * DHEAD) {
        float s = 0.f;
        for (int b = 0; b < BPH; b++) s += g_part_kss[b][i];
        g_kssum[i] = s;
    }
    if (i < CIN) {
        float s = 0.f;
        for (int b = 0; b < BPH; b++) s += g_part_cs[b][i];
        g_colsum[i] = s;
    }
}

// =====================================================================
// Phase B: pure out-GEMM from precomputed qn  (2 blocks/SM, grid 74x4)
// smem floats: qsn 4352 | kvs 16384 | kss 64 | cs 256 | red2 256 | rno 64
//  = 21376 (85504 B)
// =====================================================================
__global__ __launch_bounds__(NTHR, 2)
void phaseB_kernel(float* __restrict__ out)
{
    const int h = blockIdx.y, tid = threadIdx.x;
    const int lane = tid & 31, w = tid >> 5;
    const int gq = lane >> 2, ct = lane & 3;

    float* qsn  = smf;             // [64][QS]
    float* kvs  = qsn + 4352;      // [64][256] swizzled: phys_c = c ^ (8*(m&3))
    float* kss  = kvs + 16384;
    float* cs   = kss + 64;
    float* red2 = cs + 256;        // [256]
    float* rno  = red2 + 256;      // [64]

    for (int i = tid; i < 16384; i += NTHR) {
        int m = i >> 8, c = i & 255;
        kvs[m * 256 + (c ^ (8 * (m & 3)))] = rna(g_kvs[h * 16384 + m * 256 + c]);
    }
    if (tid < 64) kss[tid] = g_kssum[h * 64 + tid];
    cs[tid] = g_colsum[tid];

    const int sn = w >> 2, cq = w & 3;   // out: 2 row-slabs(32) x 4 c-quarters(64)

    // prefetch first qn tile: 64x64 floats, 16 per thread
    float4 pf[4];
    {
        const int base = blockIdx.x * TILE;
        #pragma unroll
        for (int j = 0; j < 4; j++) {
            int s = tid + j * NTHR;
            int n = s >> 4, c4 = (s & 15) * 4;
            pf[j] = *(const float4*)(g_qn + ((size_t)h * NPAD + base + n) * DHEAD + c4);
        }
    }
    __syncthreads();

    for (int tile = blockIdx.x; tile < NT; tile += BPHB) {
        const int base = tile * TILE;
        const int valid = (NNODES - base < TILE) ? (NNODES - base) : TILE;

        // ---- store qn tile
        #pragma unroll
        for (int j = 0; j < 4; j++) {
            int s = tid + j * NTHR;
            int n = s >> 4, c4 = (s & 15) * 4;
            *(float4*)(qsn + n * QS + c4) = pf[j];
        }
        __syncthreads();

        // ---- prefetch next tile
        if (tile + BPHB < NT) {
            const int nb = (tile + BPHB) * TILE;
            #pragma unroll
            for (int j = 0; j < 4; j++) {
                int s = tid + j * NTHR;
                int n = s >> 4, c4 = (s & 15) * 4;
                pf[j] = *(const float4*)(g_qn + ((size_t)h * NPAD + nb + n) * DHEAD + c4);
            }
        }

        // ---- normalizer: dot(qn, ks_sum) per row
        {
            int n = tid >> 2, q = tid & 3;
            const float* qr = qsn + n * QS + q * 16;
            const float* kr = kss + q * 16;
            float d = 0.f;
            #pragma unroll
            for (int i2 = 0; i2 < 16; i2++) d += qr[i2] * kr[i2];
            red2[n * 4 + q] = d;
        }
        __syncthreads();
        if (tid < 64) {
            float d = red2[tid*4] + red2[tid*4+1] + red2[tid*4+2] + red2[tid*4+3];
            rno[tid] = 1.0f / (d + (float)NNODES);
        }
        __syncthreads();

        // ---- out = (qn @ kvs + colsum) * rno
        {
            float oc[2][8][4];
            #pragma unroll
            for (int mi = 0; mi < 2; mi++)
                #pragma unroll
                for (int t = 0; t < 8; t++) {
                    oc[mi][t][0]=0.f; oc[mi][t][1]=0.f; oc[mi][t][2]=0.f; oc[mi][t][3]=0.f;
                }
            int nbase = sn * 32 + gq;
            #pragma unroll
            for (int kb = 0; kb < 8; kb++) {
                uint4 a0, a1;
                {
                    const float* ap = qsn + nbase * QS + kb * 8 + ct;
                    a0.x = fu(rna(ap[0]));          a0.y = fu(rna(ap[8 * QS]));
                    a0.z = fu(rna(ap[4]));          a0.w = fu(rna(ap[8 * QS + 4]));
                    const float* ap1 = ap + 16 * QS;
                    a1.x = fu(rna(ap1[0]));         a1.y = fu(rna(ap1[8 * QS]));
                    a1.z = fu(rna(ap1[4]));         a1.w = fu(rna(ap1[8 * QS + 4]));
                }
                const float* kp0 = kvs + (kb * 8 + ct) * 256;
                const float* kp1 = kvs + (kb * 8 + ct + 4) * 256;
                const int sw = 8 * ct;
                #pragma unroll
                for (int t = 0; t < 8; t++) {
                    int c = cq * 64 + t * 8 + gq;
                    uint2 b; b.x = fu(kp0[c ^ sw]); b.y = fu(kp1[c ^ sw]);
                    mma8(oc[0][t], a0, b);
                    mma8(oc[1][t], a1, b);
                }
            }
            #pragma unroll
            for (int mi = 0; mi < 2; mi++) {
                int n0 = sn * 32 + mi * 16 + gq;
                float r0v = rno[n0], r1v = rno[n0 + 8];
                #pragma unroll
                for (int t = 0; t < 8; t++) {
                    int c0 = cq * 64 + t * 8 + 2 * ct;
                    float cv0 = cs[c0], cv1 = cs[c0 + 1];
                    if (n0 < valid)
                        *(float2*)(out + (size_t)(base + n0) * (NHEADS * CIN) + h * CIN + c0) =
                            make_float2((oc[mi][t][0] + cv0) * r0v, (oc[mi][t][1] + cv1) * r0v);
                    if (n0 + 8 < valid)
                        *(float2*)(out + (size_t)(base + n0 + 8) * (NHEADS * CIN) + h * CIN + c0) =
                            make_float2((oc[mi][t][2] + cv0) * r1v, (oc[mi][t][3] + cv1) * r1v);
                }
            }
        }
        __syncthreads();
    }
}

// =====================================================================
extern "C" void kernel_launch(void* const* d_in, const int* in_sizes, int n_in,
                              void* d_out, int out_size)
{
    const float* x    = (const float*)d_in[0];
    const float* Wq_w = (const float*)d_in[1];
    const float* Wq_b = (const float*)d_in[2];
    const float* Wk_w = (const float*)d_in[3];
    const float* Wk_b = (const float*)d_in[4];
    float* out = (float*)d_out;

    const int smemA = 56384 * (int)sizeof(float);   // 225536 B
    const int smemB = 21376 * (int)sizeof(float);   // 85504 B

    cudaFuncSetAttribute(phaseA_kernel, cudaFuncAttributeMaxDynamicSharedMemorySize, smemA);
    cudaFuncSetAttribute(phaseB_kernel, cudaFuncAttributeMaxDynamicSharedMemorySize, smemB);

    phaseA_kernel<<<dim3(BPH, NHEADS), NTHR, smemA>>>(x, Wk_w, Wk_b, Wq_w, Wq_b);
    reduce_kernel<<<256, 256>>>();
    phaseB_kernel<<<dim3(BPHB, NHEADS), NTHR, smemB>>>(out);
}

// round 15
// speedup vs baseline: 1.3029x; 1.0455x over previous
#include <cuda_runtime.h>
#include <math.h>
#include <stdint.h>

#define NNODES 100000
#define CIN    256
#define NHEADS 4
#define DHEAD  64
#define BPH    37
#define BPHB   74
#define TILE   64
#define NT     ((NNODES + TILE - 1) / TILE)   // 1563
#define NPAD   (NT * TILE)                    // 100032
#define XS     260                            // xsA stride (A-frag clean)
#define KS     72                             // ks stride  (transposed-A clean)
#define QS     68                             // qn stride  (A-frag clean)
#define NTHR   256

// ---------------- helpers ----------------
__device__ __forceinline__ float rna(float f) {
    unsigned int u;
    asm("cvt.rna.tf32.f32 %0, %1;" : "=r"(u) : "f"(f));
    return __uint_as_float(u);
}
__device__ __forceinline__ unsigned int fu(float f) { return __float_as_uint(f); }
__device__ __forceinline__ void mma8(float c[4], uint4 a, uint2 b) {
    asm volatile("mma.sync.aligned.m16n8k8.row.col.f32.tf32.tf32.f32 "
        "{%0,%1,%2,%3}, {%4,%5,%6,%7}, {%8,%9}, {%0,%1,%2,%3};"
        : "+f"(c[0]), "+f"(c[1]), "+f"(c[2]), "+f"(c[3])
        : "r"(a.x), "r"(a.y), "r"(a.z), "r"(a.w), "r"(b.x), "r"(b.y));
}

// ---------------- device scratch ----------------
__device__ float g_qn[(size_t)NHEADS * NPAD * DHEAD];   // normalized q, fp32
__device__ float g_part_kvs[BPH][NHEADS * DHEAD * CIN];
__device__ float g_part_kss[BPH][NHEADS * DHEAD];
__device__ float g_part_cs [BPH][CIN];
__device__ float g_kvs   [NHEADS * DHEAD * CIN];
__device__ float g_kssum [NHEADS * DHEAD];
__device__ float g_colsum[CIN];

extern __shared__ float smf[];

// =====================================================================
// Phase A: fused k/q-proj (2x4 warp tiling, b-reuse 2x) + kv + qn STG
// smem floats: xsA 16640 | wtk 16384 | wtq 16384 | ks 4608 | biask 64 |
//  biasq 64 | kss 64 | red 256 | redq 256 | inv 64 | qinv 64 | csred 1024
//  = 55872 (223488 B)
// =====================================================================
__global__ __launch_bounds__(NTHR, 1)
void phaseA_kernel(const float* __restrict__ x,
                   const float* __restrict__ Wk,
                   const float* __restrict__ bk,
                   const float* __restrict__ Wq,
                   const float* __restrict__ bq)
{
    const int h = blockIdx.y, bx = blockIdx.x, tid = threadIdx.x;
    const int lane = tid & 31, w = tid >> 5;
    const int gq = lane >> 2, ct = lane & 3;

    float* xsA   = smf;              // [64][260]
    float* wtk   = xsA + 16640;      // [256][64] swizzled: phys_m = m ^ (8*(c&3))
    float* wtq   = wtk + 16384;      // [256][64] swizzled
    float* ks    = wtq + 16384;      // [64][KS] raw (bias added, NOT normalized)
    float* biask = ks + 4608;
    float* biasq = biask + 64;
    float* kss   = biasq + 64;
    float* red   = kss + 64;         // [256]  (row x quarter)
    float* redq  = red + 256;        // [256]
    float* inv   = redq + 256;       // [64]
    float* qinv  = inv + 64;         // [64]
    float* csred = qinv + 64;        // [256][4]

    for (int i = tid; i < 16384; i += NTHR) {
        int c = i >> 6, m = i & 63;
        int sm = m ^ (8 * (c & 3));
        wtk[c * 64 + sm] = rna(Wk[(h * 64 + m) * 256 + c]);
        wtq[c * 64 + sm] = rna(Wq[(h * 64 + m) * 256 + c]);
    }
    if (tid < 64) { biask[tid] = bk[h * 64 + tid]; biasq[tid] = bq[h * 64 + tid]; kss[tid] = 0.f; }

    const int p2 = w & 1, nq = w >> 1;   // proj: 2 row-slabs(32) x 4 col-quarters(16)
    const int km = w >> 2, cq = w & 3;   // kv:   2 m-slabs(32) x 4 c-quarters(64)

    float kvC[2][8][4];
    #pragma unroll
    for (int mi = 0; mi < 2; mi++)
        #pragma unroll
        for (int t = 0; t < 8; t++) {
            kvC[mi][t][0]=0.f; kvC[mi][t][1]=0.f; kvC[mi][t][2]=0.f; kvC[mi][t][3]=0.f;
        }
    float4 csacc = make_float4(0.f, 0.f, 0.f, 0.f);

    float4 pf[8];
    {
        const int base = bx * TILE;
        const int valid = (NNODES - base < TILE) ? (NNODES - base) : TILE;
        #pragma unroll
        for (int j = 0; j < 8; j++) {
            int i = tid + j * NTHR;
            int n = i >> 6, c4 = (i & 63) << 2;
            pf[j] = (n < valid) ? *(const float4*)(x + (size_t)(base + n) * CIN + c4)
                                : make_float4(0.f, 0.f, 0.f, 0.f);
        }
    }
    __syncthreads();

    for (int tile = bx; tile < NT; tile += BPH) {
        const int base = tile * TILE;
        const int valid = (NNODES - base < TILE) ? (NNODES - base) : TILE;

        // ---- store tile + colsum partials
        #pragma unroll
        for (int j = 0; j < 8; j++) {
            int i = tid + j * NTHR;
            int n = i >> 6, c4 = (i & 63) << 2;
            float4 v = pf[j];
            csacc.x += v.x; csacc.y += v.y; csacc.z += v.z; csacc.w += v.w;
            *(float4*)(xsA + n * XS + c4) =
                make_float4(rna(v.x), rna(v.y), rna(v.z), rna(v.w));
        }
        #pragma unroll
        for (int j = 8; j < 16; j++) {
            int i = tid + j * NTHR;
            int n = i >> 6, c4 = (i & 63) << 2;
            float4 v = (n < valid) ? *(const float4*)(x + (size_t)(base + n) * CIN + c4)
                                   : make_float4(0.f, 0.f, 0.f, 0.f);
            csacc.x += v.x; csacc.y += v.y; csacc.z += v.z; csacc.w += v.w;
            *(float4*)(xsA + n * XS + c4) =
                make_float4(rna(v.x), rna(v.y), rna(v.z), rna(v.w));
        }
        __syncthreads();

        if (tile + BPH < NT) {
            const int nb = (tile + BPH) * TILE;
            const int nv = (NNODES - nb < TILE) ? (NNODES - nb) : TILE;
            #pragma unroll
            for (int j = 0; j < 8; j++) {
                int i = tid + j * NTHR;
                int n = i >> 6, c4 = (i & 63) << 2;
                pf[j] = (n < nv) ? *(const float4*)(x + (size_t)(nb + n) * CIN + c4)
                                 : make_float4(0.f, 0.f, 0.f, 0.f);
            }
        }

        // ---- fused k/q-proj: 32 rows x 16 cols per warp (b-frags reused 2x)
        float qc[2][2][4];
        {
            float pck[2][2][4];
            #pragma unroll
            for (int mi = 0; mi < 2; mi++)
                #pragma unroll
                for (int t = 0; t < 2; t++) {
                    pck[mi][t][0]=0.f; pck[mi][t][1]=0.f; pck[mi][t][2]=0.f; pck[mi][t][3]=0.f;
                    qc [mi][t][0]=0.f; qc [mi][t][1]=0.f; qc [mi][t][2]=0.f; qc [mi][t][3]=0.f;
                }
            #pragma unroll 2
            for (int kb = 0; kb < 32; kb++) {
                const float* xr = xsA + (p2 * 32 + gq) * XS + kb * 8 + ct;
                uint4 a0, a1;
                a0.x = fu(xr[0]);       a0.y = fu(xr[8 * XS]);
                a0.z = fu(xr[4]);       a0.w = fu(xr[8 * XS + 4]);
                const float* xr2 = xr + 16 * XS;
                a1.x = fu(xr2[0]);      a1.y = fu(xr2[8 * XS]);
                a1.z = fu(xr2[4]);      a1.w = fu(xr2[8 * XS + 4]);
                #pragma unroll
                for (int t = 0; t < 2; t++) {
                    int off = (kb * 8 + ct) * 64 + ((nq * 16 + t * 8 + gq) ^ (8 * ct));
                    uint2 b;
                    b.x = fu(wtk[off]); b.y = fu(wtk[off + 4 * 64]);
                    mma8(pck[0][t], a0, b);
                    mma8(pck[1][t], a1, b);
                    uint2 b2;
                    b2.x = fu(wtq[off]); b2.y = fu(wtq[off + 4 * 64]);
                    mma8(qc[0][t], a0, b2);
                    mma8(qc[1][t], a1, b2);
                }
            }
            #pragma unroll
            for (int mi = 0; mi < 2; mi++) {
                int r0 = p2 * 32 + mi * 16 + gq;
                float nrm0 = 0.f, nrm1 = 0.f, qn0 = 0.f, qn1 = 0.f;
                #pragma unroll
                for (int t = 0; t < 2; t++) {
                    int cb = nq * 16 + t * 8 + 2 * ct;
                    float bk0 = biask[cb], bk1 = biask[cb + 1];
                    float bq0 = biasq[cb], bq1 = biasq[cb + 1];
                    float v0 = pck[mi][t][0] + bk0, v1 = pck[mi][t][1] + bk1;
                    float v2 = pck[mi][t][2] + bk0, v3 = pck[mi][t][3] + bk1;
                    *(float2*)(ks + r0 * KS + cb)       = make_float2(v0, v1);
                    *(float2*)(ks + (r0 + 8) * KS + cb) = make_float2(v2, v3);
                    nrm0 += v0 * v0 + v1 * v1;
                    nrm1 += v2 * v2 + v3 * v3;
                    qc[mi][t][0] += bq0; qc[mi][t][1] += bq1;
                    qc[mi][t][2] += bq0; qc[mi][t][3] += bq1;
                    qn0 += qc[mi][t][0] * qc[mi][t][0] + qc[mi][t][1] * qc[mi][t][1];
                    qn1 += qc[mi][t][2] * qc[mi][t][2] + qc[mi][t][3] * qc[mi][t][3];
                }
                nrm0 += __shfl_xor_sync(0xffffffffu, nrm0, 1);
                nrm0 += __shfl_xor_sync(0xffffffffu, nrm0, 2);
                nrm1 += __shfl_xor_sync(0xffffffffu, nrm1, 1);
                nrm1 += __shfl_xor_sync(0xffffffffu, nrm1, 2);
                qn0 += __shfl_xor_sync(0xffffffffu, qn0, 1);
                qn0 += __shfl_xor_sync(0xffffffffu, qn0, 2);
                qn1 += __shfl_xor_sync(0xffffffffu, qn1, 1);
                qn1 += __shfl_xor_sync(0xffffffffu, qn1, 2);
                if (ct == 0) {
                    red [r0 * 4 + nq] = nrm0;  red [(r0 + 8) * 4 + nq] = nrm1;
                    redq[r0 * 4 + nq] = qn0;   redq[(r0 + 8) * 4 + nq] = qn1;
                }
            }
        }
        __syncthreads();

        if (tid < 64) {
            float s = red[tid*4] + red[tid*4+1] + red[tid*4+2] + red[tid*4+3];
            inv[tid] = (tid < valid) ? rsqrtf(s) : 0.f;
        } else if (tid < 128) {
            int n = tid - 64;
            float s = redq[n*4] + redq[n*4+1] + redq[n*4+2] + redq[n*4+3];
            qinv[n] = (n < valid) ? rsqrtf(s) : 0.f;
        }
        __syncthreads();

        // ---- qn store to gmem (registers -> STG)
        {
            #pragma unroll
            for (int mi = 0; mi < 2; mi++) {
                int r0 = p2 * 32 + mi * 16 + gq;
                float iq0 = qinv[r0], iq1 = qinv[r0 + 8];
                float* q0 = g_qn + ((size_t)h * NPAD + base + r0) * DHEAD;
                float* q1 = g_qn + ((size_t)h * NPAD + base + r0 + 8) * DHEAD;
                #pragma unroll
                for (int t = 0; t < 2; t++) {
                    int cb = nq * 16 + t * 8 + 2 * ct;
                    *(float2*)(q0 + cb) = make_float2(qc[mi][t][0] * iq0, qc[mi][t][1] * iq0);
                    *(float2*)(q1 + cb) = make_float2(qc[mi][t][2] * iq1, qc[mi][t][3] * iq1);
                }
            }
        }

        // ---- ks_sum partials from raw ks (normalize folded)
        {
            int m = tid & 63, rg = tid >> 6;
            float s = 0.f;
            #pragma unroll
            for (int r = 0; r < 16; r++) {
                int n = rg * 16 + r;
                s += rna(ks[n * KS + m] * inv[n]);
            }
            red[rg * 64 + m] = s;
        }

        // ---- kv += ks^T @ x  (b-frags from xsA)
        {
            #pragma unroll
            for (int kb = 0; kb < 8; kb++) {
                int n0 = kb * 8 + ct;
                float iv0 = inv[n0], iv1 = inv[n0 + 4];
                uint4 a0, a1;
                {
                    const float* kp = ks + n0 * KS + km * 32 + gq;
                    a0.x = fu(rna(kp[0]  * iv0));          a0.y = fu(rna(kp[8]  * iv0));
                    a0.z = fu(rna(kp[4 * KS] * iv1));      a0.w = fu(rna(kp[4 * KS + 8] * iv1));
                    a1.x = fu(rna(kp[16] * iv0));          a1.y = fu(rna(kp[24] * iv0));
                    a1.z = fu(rna(kp[4 * KS + 16] * iv1)); a1.w = fu(rna(kp[4 * KS + 24] * iv1));
                }
                const float* xb0 = xsA + n0 * XS;
                const float* xb1 = xsA + (n0 + 4) * XS;
                #pragma unroll
                for (int t = 0; t < 8; t++) {
                    int c = cq * 64 + t * 8 + gq;
                    uint2 b; b.x = fu(xb0[c]); b.y = fu(xb1[c]);
                    mma8(kvC[0][t], a0, b);
                    mma8(kvC[1][t], a1, b);
                }
            }
        }
        __syncthreads();

        if (tid < 64)
            kss[tid] += red[tid] + red[64 + tid] + red[128 + tid] + red[192 + tid];
    }
    __syncthreads();

    {
        float* dst = g_part_kvs[bx] + h * (DHEAD * CIN);
        #pragma unroll
        for (int mi = 0; mi < 2; mi++)
            #pragma unroll
            for (int t = 0; t < 8; t++) {
                int c0 = cq * 64 + t * 8 + 2 * ct;
                int m0 = km * 32 + mi * 16 + gq;
                dst[m0 * 256 + c0]           = kvC[mi][t][0];
                dst[m0 * 256 + c0 + 1]       = kvC[mi][t][1];
                dst[(m0 + 8) * 256 + c0]     = kvC[mi][t][2];
                dst[(m0 + 8) * 256 + c0 + 1] = kvC[mi][t][3];
            }
    }
    if (tid < 64) g_part_kss[bx][h * 64 + tid] = kss[tid];
    {
        int c4 = (tid & 63) * 4, grp = tid >> 6;
        csred[(c4+0)*4+grp] = csacc.x; csred[(c4+1)*4+grp] = csacc.y;
        csred[(c4+2)*4+grp] = csacc.z; csred[(c4+3)*4+grp] = csacc.w;
    }
    __syncthreads();
    if (h == 0)
        g_part_cs[bx][tid] = csred[tid*4] + csred[tid*4+1] + csred[tid*4+2] + csred[tid*4+3];
}

// =====================================================================
// Reduce
// =====================================================================
__global__ void reduce_kernel()
{
    int i = blockIdx.x * 256 + threadIdx.x;
    if (i < NHEADS * DHEAD * CIN) {
        float s = 0.f;
        #pragma unroll 1
        for (int b = 0; b < BPH; b++) s += g_part_kvs[b][i];
        g_kvs[i] = s;
    }
    if (i < NHEADS * DHEAD) {
        float s = 0.f;
        for (int b = 0; b < BPH; b++) s += g_part_kss[b][i];
        g_kssum[i] = s;
    }
    if (i < CIN) {
        float s = 0.f;
        for (int b = 0; b < BPH; b++) s += g_part_cs[b][i];
        g_colsum[i] = s;
    }
}

// =====================================================================
// Phase B: pure out-GEMM from precomputed qn  (2 blocks/SM)
// smem floats: qsn 4352 | kvs 16384 | kss 64 | cs 256 | red2 256 | rno 64
//  = 21376 (85504 B)
// =====================================================================
__global__ __launch_bounds__(NTHR, 2)
void phaseB_kernel(float* __restrict__ out)
{
    const int h = blockIdx.y, tid = threadIdx.x;
    const int lane = tid & 31, w = tid >> 5;
    const int gq = lane >> 2, ct = lane & 3;

    float* qsn  = smf;             // [64][QS]
    float* kvs  = qsn + 4352;      // [64][256] swizzled: phys_c = c ^ (8*(m&3))
    float* kss  = kvs + 16384;
    float* cs   = kss + 64;
    float* red2 = cs + 256;        // [256]
    float* rno  = red2 + 256;      // [64]

    for (int i = tid; i < 16384; i += NTHR) {
        int m = i >> 8, c = i & 255;
        kvs[m * 256 + (c ^ (8 * (m & 3)))] = rna(g_kvs[h * 16384 + m * 256 + c]);
    }
    if (tid < 64) kss[tid] = g_kssum[h * 64 + tid];
    cs[tid] = g_colsum[tid];

    const int sn = w >> 2, cq = w & 3;

    float4 pf[4];
    {
        const int base = blockIdx.x * TILE;
        #pragma unroll
        for (int j = 0; j < 4; j++) {
            int s = tid + j * NTHR;
            int n = s >> 4, c4 = (s & 15) * 4;
            pf[j] = *(const float4*)(g_qn + ((size_t)h * NPAD + base + n) * DHEAD + c4);
        }
    }
    __syncthreads();

    for (int tile = blockIdx.x; tile < NT; tile += BPHB) {
        const int base = tile * TILE;
        const int valid = (NNODES - base < TILE) ? (NNODES - base) : TILE;

        #pragma unroll
        for (int j = 0; j < 4; j++) {
            int s = tid + j * NTHR;
            int n = s >> 4, c4 = (s & 15) * 4;
            *(float4*)(qsn + n * QS + c4) = pf[j];
        }
        __syncthreads();

        if (tile + BPHB < NT) {
            const int nb = (tile + BPHB) * TILE;
            #pragma unroll
            for (int j = 0; j < 4; j++) {
                int s = tid + j * NTHR;
                int n = s >> 4, c4 = (s & 15) * 4;
                pf[j] = *(const float4*)(g_qn + ((size_t)h * NPAD + nb + n) * DHEAD + c4);
            }
        }

        // ---- normalizer: dot(qn, ks_sum) per row
        {
            int n = tid >> 2, q = tid & 3;
            const float* qr = qsn + n * QS + q * 16;
            const float* kr = kss + q * 16;
            float d = 0.f;
            #pragma unroll
            for (int i2 = 0; i2 < 16; i2++) d += qr[i2] * kr[i2];
            red2[n * 4 + q] = d;
        }
        __syncthreads();
        if (tid < 64) {
            float d = red2[tid*4] + red2[tid*4+1] + red2[tid*4+2] + red2[tid*4+3];
            rno[tid] = 1.0f / (d + (float)NNODES);
        }
        __syncthreads();

        // ---- out = (qn @ kvs + colsum) * rno
        {
            float oc[2][8][4];
            #pragma unroll
            for (int mi = 0; mi < 2; mi++)
                #pragma unroll
                for (int t = 0; t < 8; t++) {
                    oc[mi][t][0]=0.f; oc[mi][t][1]=0.f; oc[mi][t][2]=0.f; oc[mi][t][3]=0.f;
                }
            int nbase = sn * 32 + gq;
            #pragma unroll
            for (int kb = 0; kb < 8; kb++) {
                uint4 a0, a1;
                {
                    const float* ap = qsn + nbase * QS + kb * 8 + ct;
                    a0.x = fu(rna(ap[0]));          a0.y = fu(rna(ap[8 * QS]));
                    a0.z = fu(rna(ap[4]));          a0.w = fu(rna(ap[8 * QS + 4]));
                    const float* ap1 = ap + 16 * QS;
                    a1.x = fu(rna(ap1[0]));         a1.y = fu(rna(ap1[8 * QS]));
                    a1.z = fu(rna(ap1[4]));         a1.w = fu(rna(ap1[8 * QS + 4]));
                }
                const float* kp0 = kvs + (kb * 8 + ct) * 256;
                const float* kp1 = kvs + (kb * 8 + ct + 4) * 256;
                const int sw = 8 * ct;
                #pragma unroll
                for (int t = 0; t < 8; t++) {
                    int c = cq * 64 + t * 8 + gq;
                    uint2 b; b.x = fu(kp0[c ^ sw]); b.y = fu(kp1[c ^ sw]);
                    mma8(oc[0][t], a0, b);
                    mma8(oc[1][t], a1, b);
                }
            }
            #pragma unroll
            for (int mi = 0; mi < 2; mi++) {
                int n0 = sn * 32 + mi * 16 + gq;
                float r0v = rno[n0], r1v = rno[n0 + 8];
                #pragma unroll
                for (int t = 0; t < 8; t++) {
                    int c0 = cq * 64 + t * 8 + 2 * ct;
                    float cv0 = cs[c0], cv1 = cs[c0 + 1];
                    if (n0 < valid)
                        *(float2*)(out + (size_t)(base + n0) * (NHEADS * CIN) + h * CIN + c0) =
                            make_float2((oc[mi][t][0] + cv0) * r0v, (oc[mi][t][1] + cv1) * r0v);
                    if (n0 + 8 < valid)
                        *(float2*)(out + (size_t)(base + n0 + 8) * (NHEADS * CIN) + h * CIN + c0) =
                            make_float2((oc[mi][t][2] + cv0) * r1v, (oc[mi][t][3] + cv1) * r1v);
                }
            }
        }
        __syncthreads();
    }
}

// =====================================================================
extern "C" void kernel_launch(void* const* d_in, const int* in_sizes, int n_in,
                              void* d_out, int out_size)
{
    const float* x    = (const float*)d_in[0];
    const float* Wq_w = (const float*)d_in[1];
    const float* Wq_b = (const float*)d_in[2];
    const float* Wk_w = (const float*)d_in[3];
    const float* Wk_b = (const float*)d_in[4];
    float* out = (float*)d_out;

    const int smemA = 55872 * (int)sizeof(float);   // 223488 B
    const int smemB = 21376 * (int)sizeof(float);   // 85504 B

    cudaFuncSetAttribute(phaseA_kernel, cudaFuncAttributeMaxDynamicSharedMemorySize, smemA);
    cudaFuncSetAttribute(phaseB_kernel, cudaFuncAttributeMaxDynamicSharedMemorySize, smemB);

    phaseA_kernel<<<dim3(BPH, NHEADS), NTHR, smemA>>>(x, Wk_w, Wk_b, Wq_w, Wq_b);
    reduce_kernel<<<256, 256>>>();
    phaseB_kernel<<<dim3(BPHB, NHEADS), NTHR, smemB>>>(out);
}